// round 8
// baseline (speedup 1.0000x reference)
#include <cuda_runtime.h>
#include <cuda_bf16.h>
#include <cstdint>

// ---------------- problem constants ----------------
#define N_NODES_MAX 50000
#define N_EDGES_MAX 800000
#define N_GRAPHS_MAX 1000
#define HID 128
#define HIDH 64
#define KPAD 128
#define EPS 1e-5f
#define SCAN_B 1024
#define MAX_BLOCKS ((N_NODES_MAX + SCAN_B - 1) / SCAN_B)

// ---------------- scratch (device globals, allocation-free) ----------------
__device__ __align__(16) float g_y[N_NODES_MAX * HID];
__device__ __align__(16) float g_z[N_NODES_MAX * HID];
__device__ __align__(16) float g_h[N_NODES_MAX * HID];
__device__ __align__(16) __nv_bfloat16 g_ax_hi[N_NODES_MAX * KPAD];
__device__ __align__(16) __nv_bfloat16 g_ax_lo[N_NODES_MAX * KPAD];
__device__ __align__(16) __nv_bfloat16 g_ah_hi[N_NODES_MAX * KPAD];
__device__ __align__(16) __nv_bfloat16 g_ah_lo[N_NODES_MAX * KPAD];
__device__ __align__(16) __nv_bfloat16 g_bw_hi[3][256 * KPAD];   // [Wn|Wr]^T hi, [n][k]
__device__ __align__(16) __nv_bfloat16 g_bw_lo[3][256 * KPAD];
__device__ int   g_is64;
__device__ int   g_indeg[N_NODES_MAX];
__device__ int   g_rowexcl[N_NODES_MAX];
__device__ int   g_bsum[MAX_BLOCKS];
__device__ int   g_bsumex[MAX_BLOCKS];
__device__ int   g_row_start[N_NODES_MAX + 1];
__device__ int   g_epos[N_NODES_MAX];
__device__ int   g_esrc[N_EDGES_MAX];
__device__ int   g_gstart[N_GRAPHS_MAX + 1];
__device__ float g_stat3[3][2 * HID];
__device__ __align__(16) float g_pooled[N_GRAPHS_MAX * HID];

// ---------------- index-width handling ----------------
__device__ __forceinline__ int ld_idx(const void* p, long long i, int is64) {
    if (is64) return (int)((const long long*)p)[i];
    return ((const int*)p)[i];
}

// ---------------- combined prep: flag init + zero indeg + zero stats -------
__global__ void prep0_kernel(int N) {
    int i = blockIdx.x * blockDim.x + threadIdx.x;
    if (i == 0) g_is64 = 1;
    if (i < N) g_indeg[i] = 0;
    if (i < 3 * 2 * HID) ((float*)g_stat3)[i] = 0.f;
}

__global__ void detect_kernel(const void* ei, int n_i32) {
    int i = blockIdx.x * blockDim.x + threadIdx.x;
    int idx = 2 * i + 1;
    if (idx < n_i32 && ((const int*)ei)[idx] != 0) g_is64 = 0;
}

// ---------------- CSR build ----------------
__global__ void count_edges_kernel(const void* __restrict__ ei, int E) {
    int e = blockIdx.x * blockDim.x + threadIdx.x;
    if (e >= E) return;
    atomicAdd(&g_indeg[ld_idx(ei, (long long)E + e, g_is64)], 1);
}

__global__ void scan1_kernel(int N) {
    __shared__ int sh[SCAN_B];
    int i = blockIdx.x * SCAN_B + threadIdx.x;
    int v = (i < N) ? g_indeg[i] : 0;
    sh[threadIdx.x] = v;
    __syncthreads();
    #pragma unroll
    for (int off = 1; off < SCAN_B; off <<= 1) {
        int t = 0;
        if (threadIdx.x >= off) t = sh[threadIdx.x - off];
        __syncthreads();
        sh[threadIdx.x] += t;
        __syncthreads();
    }
    if (i < N) g_rowexcl[i] = sh[threadIdx.x] - v;
    if (threadIdx.x == SCAN_B - 1) g_bsum[blockIdx.x] = sh[SCAN_B - 1];
}

__global__ void scan2_kernel(int nblocks) {
    if (threadIdx.x == 0) {
        int run = 0;
        for (int b = 0; b < nblocks; b++) { int t = g_bsum[b]; g_bsumex[b] = run; run += t; }
    }
}

__global__ void scan3_kernel(int N, int E) {
    int i = blockIdx.x * blockDim.x + threadIdx.x;
    if (i < N) {
        int v = g_rowexcl[i] + g_bsumex[i >> 10];
        g_row_start[i] = v;
        g_epos[i] = v;
    }
    if (i == 0) g_row_start[N] = E;
}

__global__ void fill_edges_kernel(const void* __restrict__ ei, int E) {
    int e = blockIdx.x * blockDim.x + threadIdx.x;
    if (e >= E) return;
    int is64 = g_is64;
    int s = ld_idx(ei, e, is64);
    int d = ld_idx(ei, (long long)E + e, is64);
    g_esrc[atomicAdd(&g_epos[d], 1)] = s;
}

__global__ void gstart_kernel(const void* __restrict__ batch, int N, int G) {
    int i = blockIdx.x * blockDim.x + threadIdx.x;
    if (i > N) return;
    int is64 = g_is64;
    int cur  = (i == N) ? G : ld_idx(batch, i, is64);
    int prev = (i == 0) ? -1 : ld_idx(batch, i - 1, is64);
    for (int g = prev + 1; g <= cur && g <= G; g++) g_gstart[g] = i;
}

// ---------------- bf16 split conversions ----------------
__global__ void convert_x_kernel(const float* __restrict__ x, int N, int IN_CH) {
    int idx = blockIdx.x * blockDim.x + threadIdx.x;
    if (idx >= N * KPAD) return;
    int r = idx >> 7, k = idx & 127;
    float v = (k < IN_CH) ? x[(size_t)r * IN_CH + k] : 0.f;
    __nv_bfloat16 hi = __float2bfloat16(v);
    g_ax_hi[idx] = hi;
    g_ax_lo[idx] = __float2bfloat16(v - __bfloat162float(hi));
}

// one launch for all 3 layers: blockIdx.y = layer
__global__ void prep_weights_kernel(const float* __restrict__ Wn0, const float* __restrict__ Wr0,
                                    const float* __restrict__ Wn1, const float* __restrict__ Wr1,
                                    const float* __restrict__ Wn2, const float* __restrict__ Wr2,
                                    int IN_CH) {
    int idx = blockIdx.x * blockDim.x + threadIdx.x;
    if (idx >= 256 * KPAD) return;
    int layer = blockIdx.y;
    const float* Wn = (layer == 0) ? Wn0 : (layer == 1) ? Wn1 : Wn2;
    const float* Wr = (layer == 0) ? Wr0 : (layer == 1) ? Wr1 : Wr2;
    int K_real = (layer == 0) ? IN_CH : HID;
    int n = idx >> 7, k = idx & 127;
    float v = 0.f;
    if (k < K_real) v = (n < HID) ? Wn[(size_t)k * HID + n] : Wr[(size_t)k * HID + (n - HID)];
    __nv_bfloat16 hi = __float2bfloat16(v);
    g_bw_hi[layer][idx] = hi;
    g_bw_lo[layer][idx] = __float2bfloat16(v - __bfloat162float(hi));
}

// ---------------- mma.sync dual GEMM (merged halves) -----------------------
// One CTA computes Y(128x128) AND Z(128x128): [Y|Z] = A(128x128) @ Bcat^T(256x128)
// 3 precision passes: D = Ahi*Bhi + Ahi*Blo + Alo*Bhi
#define PITCH 272
#define A_TILE (128 * PITCH)            // 34816
#define B_TILE (256 * PITCH)            // 69632
#define SM_A_HI 0
#define SM_A_LO A_TILE
#define SM_B_HI (2 * A_TILE)
#define SM_B_LO (2 * A_TILE + B_TILE)
#define SM_TOTAL (2 * A_TILE + 2 * B_TILE)   // 208896

__device__ __forceinline__ uint32_t smem_u32(const void* p) {
    uint32_t a;
    asm("{ .reg .u64 t; cvta.to.shared.u64 t, %1; cvt.u32.u64 %0, t; }" : "=r"(a) : "l"(p));
    return a;
}

__device__ __forceinline__ void ldsm_x4(uint32_t& r0, uint32_t& r1, uint32_t& r2, uint32_t& r3,
                                        uint32_t addr) {
    asm volatile("ldmatrix.sync.aligned.m8n8.x4.shared.b16 {%0,%1,%2,%3}, [%4];"
                 : "=r"(r0), "=r"(r1), "=r"(r2), "=r"(r3) : "r"(addr));
}

__device__ __forceinline__ void mma16816(float* c, const uint32_t* a, const uint32_t* b) {
    asm volatile(
        "mma.sync.aligned.m16n8k16.row.col.f32.bf16.bf16.f32 "
        "{%0,%1,%2,%3}, {%4,%5,%6,%7}, {%8,%9}, {%0,%1,%2,%3};"
        : "+f"(c[0]), "+f"(c[1]), "+f"(c[2]), "+f"(c[3])
        : "r"(a[0]), "r"(a[1]), "r"(a[2]), "r"(a[3]), "r"(b[0]), "r"(b[1]));
}

__global__ __launch_bounds__(256, 1)
void gemm_mma_kernel(const uint4* __restrict__ a_hi, const uint4* __restrict__ a_lo,
                     const uint4* __restrict__ b_hi, const uint4* __restrict__ b_lo,
                     const float* __restrict__ bias, int M)
{
    extern __shared__ char smem[];
    uint32_t sbase = smem_u32(smem);

    int tid = threadIdx.x;
    int lane = tid & 31;
    int wid = tid >> 5;
    int wm = wid & 3;
    int wn = wid >> 2;
    int row0 = blockIdx.x * 128;

    // ---- load A tiles (128 rows) ----
    #pragma unroll
    for (int i = tid; i < 2048; i += 256) {
        int r = i >> 4, c16 = i & 15;
        int doff = r * PITCH + c16 * 16;
        uint4 vh = make_uint4(0, 0, 0, 0), vl = make_uint4(0, 0, 0, 0);
        if (row0 + r < M) {
            vh = a_hi[(size_t)(row0 + r) * 16 + c16];
            vl = a_lo[(size_t)(row0 + r) * 16 + c16];
        }
        *(uint4*)(smem + SM_A_HI + doff) = vh;
        *(uint4*)(smem + SM_A_LO + doff) = vl;
    }
    // ---- load B tiles (256 rows) ----
    #pragma unroll
    for (int i = tid; i < 4096; i += 256) {
        int r = i >> 4, c16 = i & 15;
        int doff = r * PITCH + c16 * 16;
        *(uint4*)(smem + SM_B_HI + doff) = b_hi[i];
        *(uint4*)(smem + SM_B_LO + doff) = b_lo[i];
    }
    __syncthreads();

    float acc[2][2][8][4];   // [half][mi][ni][frag]
    #pragma unroll
    for (int h = 0; h < 2; h++)
        #pragma unroll
        for (int mi = 0; mi < 2; mi++)
            #pragma unroll
            for (int ni = 0; ni < 8; ni++)
                #pragma unroll
                for (int q = 0; q < 4; q++) acc[h][mi][ni][q] = 0.f;

    uint32_t a_off[2];
    #pragma unroll
    for (int mi = 0; mi < 2; mi++)
        a_off[mi] = (uint32_t)((wm * 32 + mi * 16 + (lane & 15)) * PITCH + (lane >> 4) * 16);
    uint32_t b_off[4];
    {
        int grp = lane >> 3, rin = lane & 7;
        int radd = (grp >= 2) ? 8 : 0;
        int koff = (grp & 1) * 16;
        #pragma unroll
        for (int pi = 0; pi < 4; pi++)
            b_off[pi] = (uint32_t)((wn * 64 + pi * 16 + radd + rin) * PITCH + koff);
    }

    const uint32_t smA[3] = { sbase + SM_A_HI, sbase + SM_A_HI, sbase + SM_A_LO };
    const uint32_t smB[3] = { sbase + SM_B_HI, sbase + SM_B_LO, sbase + SM_B_HI };

    #pragma unroll
    for (int p = 0; p < 3; p++) {
        uint32_t abase = smA[p];
        uint32_t bbase = smB[p];
        #pragma unroll
        for (int k16 = 0; k16 < 8; k16++) {
            uint32_t kadd = k16 * 32;
            uint32_t afr[2][4];
            #pragma unroll
            for (int mi = 0; mi < 2; mi++)
                ldsm_x4(afr[mi][0], afr[mi][1], afr[mi][2], afr[mi][3],
                        abase + a_off[mi] + kadd);
            #pragma unroll
            for (int h = 0; h < 2; h++) {
                uint32_t bb = bbase + (uint32_t)(h * 128 * PITCH) + kadd;
                uint32_t bfr[8][2];
                #pragma unroll
                for (int pi = 0; pi < 4; pi++) {
                    uint32_t r0, r1, r2, r3;
                    ldsm_x4(r0, r1, r2, r3, bb + b_off[pi]);
                    bfr[pi * 2][0] = r0; bfr[pi * 2][1] = r1;
                    bfr[pi * 2 + 1][0] = r2; bfr[pi * 2 + 1][1] = r3;
                }
                #pragma unroll
                for (int ni = 0; ni < 8; ni++) {
                    mma16816(acc[h][0][ni], afr[0], bfr[ni]);
                    mma16816(acc[h][1][ni], afr[1], bfr[ni]);
                }
            }
        }
    }

    // ---- epilogue ----
    #pragma unroll
    for (int h = 0; h < 2; h++) {
        float* O = h ? g_z : g_y;
        #pragma unroll
        for (int mi = 0; mi < 2; mi++) {
            int r0 = row0 + wm * 32 + mi * 16 + (lane >> 2);
            #pragma unroll
            for (int ni = 0; ni < 8; ni++) {
                int c = wn * 64 + ni * 8 + (lane & 3) * 2;
                float bx = 0.f, by = 0.f;
                if (h) { bx = bias[c]; by = bias[c + 1]; }
                if (r0 < M) {
                    float2 v = make_float2(acc[h][mi][ni][0] + bx, acc[h][mi][ni][1] + by);
                    *(float2*)&O[(size_t)r0 * HID + c] = v;
                }
                if (r0 + 8 < M) {
                    float2 v = make_float2(acc[h][mi][ni][2] + bx, acc[h][mi][ni][3] + by);
                    *(float2*)&O[(size_t)(r0 + 8) * HID + c] = v;
                }
            }
        }
    }
}

// ---------------- gather-mean: Z[d] += mean_{s in N(d)} Y[s] ----------------
__global__ void aggregate_kernel(int N) {
    int d = blockIdx.x * 8 + (threadIdx.x >> 5);
    int lane = threadIdx.x & 31;
    if (d >= N) return;
    int s0 = g_row_start[d];
    int s1 = g_row_start[d + 1];
    int deg = s1 - s0;
    float inv = 1.0f / (float)(deg > 1 ? deg : 1);

    float4 acc = make_float4(0.f, 0.f, 0.f, 0.f);
    int j = s0;
    for (; j + 3 < s1; j += 4) {
        int sa = g_esrc[j];
        int sb = g_esrc[j + 1];
        int sc = g_esrc[j + 2];
        int sd = g_esrc[j + 3];
        float4 va = ((const float4*)g_y)[(size_t)sa * 32 + lane];
        float4 vb = ((const float4*)g_y)[(size_t)sb * 32 + lane];
        float4 vc = ((const float4*)g_y)[(size_t)sc * 32 + lane];
        float4 vd = ((const float4*)g_y)[(size_t)sd * 32 + lane];
        acc.x += (va.x + vb.x) + (vc.x + vd.x);
        acc.y += (va.y + vb.y) + (vc.y + vd.y);
        acc.z += (va.z + vb.z) + (vc.z + vd.z);
        acc.w += (va.w + vb.w) + (vc.w + vd.w);
    }
    for (; j < s1; j++) {
        int sa = g_esrc[j];
        float4 va = ((const float4*)g_y)[(size_t)sa * 32 + lane];
        acc.x += va.x; acc.y += va.y; acc.z += va.z; acc.w += va.w;
    }

    float4 z = ((const float4*)g_z)[(size_t)d * 32 + lane];
    z.x = fmaf(acc.x, inv, z.x);
    z.y = fmaf(acc.y, inv, z.y);
    z.z = fmaf(acc.z, inv, z.z);
    z.w = fmaf(acc.w, inv, z.w);
    ((float4*)g_z)[(size_t)d * 32 + lane] = z;
}

// ---------------- BatchNorm stats (per-layer stat buffer) ----------------
__global__ void bn_stats_kernel(int M, int layer) {
    int c = threadIdx.x;
    float s = 0.f, q = 0.f;
    for (int r = blockIdx.x; r < M; r += gridDim.x) {
        float v = g_z[(size_t)r * HID + c];
        s += v;
        q += v * v;
    }
    atomicAdd(&g_stat3[layer][c], s);
    atomicAdd(&g_stat3[layer][HID + c], q);
}

// fused: compute scale/shift per block, h = relu(z*sc+sh), emit bf16 hi/lo;
// write fp32 h only when write_h (last layer, for pooling)
__global__ void norm_relu_kernel(int M, int layer, int write_h,
                                 const float* __restrict__ gamma,
                                 const float* __restrict__ beta) {
    __shared__ float s_scale[HID];
    __shared__ float s_shift[HID];
    int tid = threadIdx.x;
    if (tid < HID) {
        float inv_m = 1.0f / (float)M;
        float mu = g_stat3[layer][tid] * inv_m;
        float var = fmaxf(g_stat3[layer][HID + tid] * inv_m - mu * mu, 0.f);
        float sc = gamma[tid] * rsqrtf(var + EPS);
        s_scale[tid] = sc;
        s_shift[tid] = beta[tid] - mu * sc;
    }
    __syncthreads();

    int idx = blockIdx.x * blockDim.x + tid;   // float4 index
    int total = M * 32;
    if (idx >= total) return;
    int c4 = idx & 31;
    float4 z = ((const float4*)g_z)[idx];
    float4 sc = ((const float4*)s_scale)[c4];
    float4 sh = ((const float4*)s_shift)[c4];
    float4 h;
    h.x = fmaxf(fmaf(z.x, sc.x, sh.x), 0.f);
    h.y = fmaxf(fmaf(z.y, sc.y, sh.y), 0.f);
    h.z = fmaxf(fmaf(z.z, sc.z, sh.z), 0.f);
    h.w = fmaxf(fmaf(z.w, sc.w, sh.w), 0.f);
    if (write_h) ((float4*)g_h)[idx] = h;

    __nv_bfloat16 hx = __float2bfloat16(h.x);
    __nv_bfloat16 hy = __float2bfloat16(h.y);
    __nv_bfloat16 hz = __float2bfloat16(h.z);
    __nv_bfloat16 hw = __float2bfloat16(h.w);
    __nv_bfloat162* phi = (__nv_bfloat162*)&g_ah_hi[(size_t)idx * 4];
    phi[0] = __nv_bfloat162(hx, hy);
    phi[1] = __nv_bfloat162(hz, hw);
    __nv_bfloat162* plo = (__nv_bfloat162*)&g_ah_lo[(size_t)idx * 4];
    plo[0] = __nv_bfloat162(__float2bfloat16(h.x - __bfloat162float(hx)),
                            __float2bfloat16(h.y - __bfloat162float(hy)));
    plo[1] = __nv_bfloat162(__float2bfloat16(h.z - __bfloat162float(hz)),
                            __float2bfloat16(h.w - __bfloat162float(hw)));
}

// ---------------- global mean pool (segmented, batch sorted) ----------------
__global__ void pool_kernel(int G) {
    int g = blockIdx.x;
    int c = threadIdx.x;
    if (g >= G) return;
    int r0 = g_gstart[g];
    int r1 = g_gstart[g + 1];
    float s = 0.f;
    for (int r = r0; r < r1; r++) s += g_h[(size_t)r * HID + c];
    int cnt = r1 - r0;
    g_pooled[(size_t)g * HID + c] = s / (float)(cnt > 1 ? cnt : 1);
}

// ---------------- MLP head ----------------
__global__ void head_kernel(const float* __restrict__ Wh1,
                            const float* __restrict__ bh1,
                            const float* __restrict__ Wh2,
                            const float* __restrict__ bh2,
                            float* __restrict__ out, int G)
{
    int g = blockIdx.x;
    int t = threadIdx.x;
    if (g >= G) return;
    float acc = bh1[t];
    #pragma unroll 8
    for (int k = 0; k < HID; k++)
        acc = fmaf(g_pooled[(size_t)g * HID + k], Wh1[k * HIDH + t], acc);
    float v = fmaxf(acc, 0.f) * Wh2[t];
    #pragma unroll
    for (int off = 16; off; off >>= 1)
        v += __shfl_down_sync(0xffffffff, v, off);
    __shared__ float sred[2];
    if ((t & 31) == 0) sred[t >> 5] = v;
    __syncthreads();
    if (t == 0) out[g] = sred[0] + sred[1] + bh2[0];
}

// ---------------- launch ----------------
extern "C" void kernel_launch(void* const* d_in, const int* in_sizes, int n_in,
                              void* d_out, int out_size) {
    const float* x     = (const float*)d_in[0];
    const void*  ei    = d_in[1];
    const void*  batch = d_in[2];

    const float* W_n0 = (const float*)d_in[3];
    const float* b0   = (const float*)d_in[4];
    const float* W_r0 = (const float*)d_in[5];
    const float* g0   = (const float*)d_in[6];
    const float* be0  = (const float*)d_in[7];

    const float* W_n1 = (const float*)d_in[8];
    const float* b1   = (const float*)d_in[9];
    const float* W_r1 = (const float*)d_in[10];
    const float* g1   = (const float*)d_in[11];
    const float* be1  = (const float*)d_in[12];

    const float* W_n2 = (const float*)d_in[13];
    const float* b2   = (const float*)d_in[14];
    const float* W_r2 = (const float*)d_in[15];
    const float* g2   = (const float*)d_in[16];
    const float* be2  = (const float*)d_in[17];

    const float* Wh1 = (const float*)d_in[18];
    const float* bh1 = (const float*)d_in[19];
    const float* Wh2 = (const float*)d_in[20];
    const float* bh2 = (const float*)d_in[21];

    float* out = (float*)d_out;

    const int N = in_sizes[2];
    const int E = in_sizes[1] / 2;
    const int G = out_size;
    const int IN_CH = in_sizes[0] / N;

    cudaFuncSetAttribute(gemm_mma_kernel, cudaFuncAttributeMaxDynamicSharedMemorySize,
                         SM_TOTAL);

    // ---- prep: flag/zero, detect dtype, CSR, segments ----
    prep0_kernel<<<(N + 255) / 256, 256>>>(N);
    detect_kernel<<<8, 256>>>(ei, in_sizes[1]);
    int nscan = (N + SCAN_B - 1) / SCAN_B;
    count_edges_kernel<<<(E + 255) / 256, 256>>>(ei, E);
    scan1_kernel<<<nscan, SCAN_B>>>(N);
    scan2_kernel<<<1, 32>>>(nscan);
    scan3_kernel<<<(N + 255) / 256, 256>>>(N, E);
    fill_edges_kernel<<<(E + 255) / 256, 256>>>(ei, E);
    gstart_kernel<<<(N + 256) / 256, 256>>>(batch, N, G);

    // ---- bf16 split preprocessing ----
    convert_x_kernel<<<(N * KPAD + 255) / 256, 256>>>(x, N, IN_CH);
    {
        dim3 wgrid((256 * KPAD + 255) / 256, 3);
        prep_weights_kernel<<<wgrid, 256>>>(W_n0, W_r0, W_n1, W_r1, W_n2, W_r2, IN_CH);
    }

    int gemm_blocks = (N + 127) / 128;
    int agg_blocks  = (N + 7) / 8;
    int norm_blocks = (N * 32 + 255) / 256;

    const float* bb[3] = {b0, b1, b2};
    const float* gg[3] = {g0, g1, g2};
    const float* be[3] = {be0, be1, be2};

    for (int l = 0; l < 3; l++) {
        const uint4* ahi;
        const uint4* alo;
        const uint4* bhi;
        const uint4* blo;
        void* p;
        cudaGetSymbolAddress(&p, (l == 0) ? g_ax_hi : g_ah_hi); ahi = (const uint4*)p;
        cudaGetSymbolAddress(&p, (l == 0) ? g_ax_lo : g_ah_lo); alo = (const uint4*)p;
        cudaGetSymbolAddress(&p, g_bw_hi); bhi = (const uint4*)p + (size_t)l * (256 * KPAD / 8);
        cudaGetSymbolAddress(&p, g_bw_lo); blo = (const uint4*)p + (size_t)l * (256 * KPAD / 8);

        gemm_mma_kernel<<<gemm_blocks, 256, SM_TOTAL>>>(ahi, alo, bhi, blo, bb[l], N);
        aggregate_kernel<<<agg_blocks, 256>>>(N);
        bn_stats_kernel<<<1024, HID>>>(N, l);
        norm_relu_kernel<<<norm_blocks, 256>>>(N, l, (l == 2) ? 1 : 0, gg[l], be[l]);
    }

    pool_kernel<<<G, HID>>>(G);
    head_kernel<<<G, HIDH>>>(Wh1, bh1, Wh2, bh2, out, G);
}

// round 9
// speedup vs baseline: 1.0511x; 1.0511x over previous
#include <cuda_runtime.h>
#include <cuda_bf16.h>
#include <cstdint>

// ---------------- problem constants ----------------
#define N_NODES_MAX 50000
#define N_EDGES_MAX 800000
#define N_GRAPHS_MAX 1000
#define HID 128
#define HIDH 64
#define KPAD 128
#define EPS 1e-5f
#define SCAN_B 1024
#define MAX_BLOCKS ((N_NODES_MAX + SCAN_B - 1) / SCAN_B)

// ---------------- scratch (device globals, allocation-free) ----------------
__device__ __align__(16) float g_y[N_NODES_MAX * HID];
__device__ __align__(16) float g_z[N_NODES_MAX * HID];
__device__ __align__(16) float g_h[N_NODES_MAX * HID];
__device__ __align__(16) __nv_bfloat16 g_ax_hi[N_NODES_MAX * KPAD];
__device__ __align__(16) __nv_bfloat16 g_ax_lo[N_NODES_MAX * KPAD];
__device__ __align__(16) __nv_bfloat16 g_ah_hi[N_NODES_MAX * KPAD];
__device__ __align__(16) __nv_bfloat16 g_ah_lo[N_NODES_MAX * KPAD];
__device__ __align__(16) __nv_bfloat16 g_bw_hi[3][256 * KPAD];   // [Wn|Wr]^T hi, [n][k]
__device__ __align__(16) __nv_bfloat16 g_bw_lo[3][256 * KPAD];
__device__ int   g_is64;
__device__ int   g_indeg[N_NODES_MAX];
__device__ int   g_rowexcl[N_NODES_MAX];
__device__ int   g_bsum[MAX_BLOCKS];
__device__ int   g_bsumex[MAX_BLOCKS];
__device__ int   g_row_start[N_NODES_MAX + 1];
__device__ int   g_epos[N_NODES_MAX];
__device__ int   g_esrc[N_EDGES_MAX];
__device__ int   g_gstart[N_GRAPHS_MAX + 1];
__device__ float g_stat3[3][2 * HID];
__device__ __align__(16) float g_pooled[N_GRAPHS_MAX * HID];

// ---------------- index-width handling ----------------
__device__ __forceinline__ int ld_idx(const void* p, long long i, int is64) {
    if (is64) return (int)((const long long*)p)[i];
    return ((const int*)p)[i];
}

// ---------------- combined prep: flag init + zero indeg + zero stats -------
__global__ void prep0_kernel(int N) {
    int i = blockIdx.x * blockDim.x + threadIdx.x;
    if (i == 0) g_is64 = 1;
    if (i < N) g_indeg[i] = 0;
    if (i < 3 * 2 * HID) ((float*)g_stat3)[i] = 0.f;
}

__global__ void detect_kernel(const void* ei, int n_i32) {
    int i = blockIdx.x * blockDim.x + threadIdx.x;
    int idx = 2 * i + 1;
    if (idx < n_i32 && ((const int*)ei)[idx] != 0) g_is64 = 0;
}

// ---------------- CSR build ----------------
__global__ void count_edges_kernel(const void* __restrict__ ei, int E) {
    int e = blockIdx.x * blockDim.x + threadIdx.x;
    if (e >= E) return;
    atomicAdd(&g_indeg[ld_idx(ei, (long long)E + e, g_is64)], 1);
}

__global__ void scan1_kernel(int N) {
    __shared__ int sh[SCAN_B];
    int i = blockIdx.x * SCAN_B + threadIdx.x;
    int v = (i < N) ? g_indeg[i] : 0;
    sh[threadIdx.x] = v;
    __syncthreads();
    #pragma unroll
    for (int off = 1; off < SCAN_B; off <<= 1) {
        int t = 0;
        if (threadIdx.x >= off) t = sh[threadIdx.x - off];
        __syncthreads();
        sh[threadIdx.x] += t;
        __syncthreads();
    }
    if (i < N) g_rowexcl[i] = sh[threadIdx.x] - v;
    if (threadIdx.x == SCAN_B - 1) g_bsum[blockIdx.x] = sh[SCAN_B - 1];
}

__global__ void scan2_kernel(int nblocks) {
    if (threadIdx.x == 0) {
        int run = 0;
        for (int b = 0; b < nblocks; b++) { int t = g_bsum[b]; g_bsumex[b] = run; run += t; }
    }
}

__global__ void scan3_kernel(int N, int E) {
    int i = blockIdx.x * blockDim.x + threadIdx.x;
    if (i < N) {
        int v = g_rowexcl[i] + g_bsumex[i >> 10];
        g_row_start[i] = v;
        g_epos[i] = v;
    }
    if (i == 0) g_row_start[N] = E;
}

__global__ void fill_edges_kernel(const void* __restrict__ ei, int E) {
    int e = blockIdx.x * blockDim.x + threadIdx.x;
    if (e >= E) return;
    int is64 = g_is64;
    int s = ld_idx(ei, e, is64);
    int d = ld_idx(ei, (long long)E + e, is64);
    g_esrc[atomicAdd(&g_epos[d], 1)] = s;
}

__global__ void gstart_kernel(const void* __restrict__ batch, int N, int G) {
    int i = blockIdx.x * blockDim.x + threadIdx.x;
    if (i > N) return;
    int is64 = g_is64;
    int cur  = (i == N) ? G : ld_idx(batch, i, is64);
    int prev = (i == 0) ? -1 : ld_idx(batch, i - 1, is64);
    for (int g = prev + 1; g <= cur && g <= G; g++) g_gstart[g] = i;
}

// ---------------- bf16 split conversions ----------------
__global__ void convert_x_kernel(const float* __restrict__ x, int N, int IN_CH) {
    int idx = blockIdx.x * blockDim.x + threadIdx.x;
    if (idx >= N * KPAD) return;
    int r = idx >> 7, k = idx & 127;
    float v = (k < IN_CH) ? x[(size_t)r * IN_CH + k] : 0.f;
    __nv_bfloat16 hi = __float2bfloat16(v);
    g_ax_hi[idx] = hi;
    g_ax_lo[idx] = __float2bfloat16(v - __bfloat162float(hi));
}

// one launch for all 3 layers: blockIdx.y = layer
__global__ void prep_weights_kernel(const float* __restrict__ Wn0, const float* __restrict__ Wr0,
                                    const float* __restrict__ Wn1, const float* __restrict__ Wr1,
                                    const float* __restrict__ Wn2, const float* __restrict__ Wr2,
                                    int IN_CH) {
    int idx = blockIdx.x * blockDim.x + threadIdx.x;
    if (idx >= 256 * KPAD) return;
    int layer = blockIdx.y;
    const float* Wn = (layer == 0) ? Wn0 : (layer == 1) ? Wn1 : Wn2;
    const float* Wr = (layer == 0) ? Wr0 : (layer == 1) ? Wr1 : Wr2;
    int K_real = (layer == 0) ? IN_CH : HID;
    int n = idx >> 7, k = idx & 127;
    float v = 0.f;
    if (k < K_real) v = (n < HID) ? Wn[(size_t)k * HID + n] : Wr[(size_t)k * HID + (n - HID)];
    __nv_bfloat16 hi = __float2bfloat16(v);
    g_bw_hi[layer][idx] = hi;
    g_bw_lo[layer][idx] = __float2bfloat16(v - __bfloat162float(hi));
}

// ---------------- mma.sync dual GEMM (split halves, 3-tile SMEM) -----------
// grid (nb, 2). blockIdx.y: 0 -> g_y (B rows 0..127), 1 -> g_z + bias.
// Passes: p1 = Ahi*Bhi, p2 = Ahi*Blo, [reload A tile with Alo], p3 = Alo*Bhi.
// 3 tiles resident (102KB) -> 2 CTAs/SM.
#define PITCH 272
#define A_TILE (128 * PITCH)            // 34816
#define SM_A    0
#define SM_B_HI A_TILE
#define SM_B_LO (2 * A_TILE)
#define SM_TOTAL (3 * A_TILE)           // 104448

__device__ __forceinline__ uint32_t smem_u32(const void* p) {
    uint32_t a;
    asm("{ .reg .u64 t; cvta.to.shared.u64 t, %1; cvt.u32.u64 %0, t; }" : "=r"(a) : "l"(p));
    return a;
}

__device__ __forceinline__ void ldsm_x4(uint32_t& r0, uint32_t& r1, uint32_t& r2, uint32_t& r3,
                                        uint32_t addr) {
    asm volatile("ldmatrix.sync.aligned.m8n8.x4.shared.b16 {%0,%1,%2,%3}, [%4];"
                 : "=r"(r0), "=r"(r1), "=r"(r2), "=r"(r3) : "r"(addr));
}

__device__ __forceinline__ void mma16816(float* c, const uint32_t* a, const uint32_t* b) {
    asm volatile(
        "mma.sync.aligned.m16n8k16.row.col.f32.bf16.bf16.f32 "
        "{%0,%1,%2,%3}, {%4,%5,%6,%7}, {%8,%9}, {%0,%1,%2,%3};"
        : "+f"(c[0]), "+f"(c[1]), "+f"(c[2]), "+f"(c[3])
        : "r"(a[0]), "r"(a[1]), "r"(a[2]), "r"(a[3]), "r"(b[0]), "r"(b[1]));
}

__global__ __launch_bounds__(256, 2)
void gemm_mma_kernel(const uint4* __restrict__ a_hi, const uint4* __restrict__ a_lo,
                     const uint4* __restrict__ b_hi, const uint4* __restrict__ b_lo,
                     const float* __restrict__ bias, int M)
{
    extern __shared__ char smem[];
    uint32_t sbase = smem_u32(smem);

    int tid = threadIdx.x;
    int lane = tid & 31;
    int wid = tid >> 5;
    int wm = wid & 3;
    int wn = wid >> 2;
    int row0 = blockIdx.x * 128;
    int half = blockIdx.y;
    int brow0 = half * 128;

    // ---- load A_hi + both B tiles ----
    #pragma unroll
    for (int i = tid; i < 2048; i += 256) {
        int r = i >> 4, c16 = i & 15;
        int doff = r * PITCH + c16 * 16;
        uint4 vh = make_uint4(0, 0, 0, 0);
        if (row0 + r < M) vh = a_hi[(size_t)(row0 + r) * 16 + c16];
        *(uint4*)(smem + SM_A + doff) = vh;
        *(uint4*)(smem + SM_B_HI + doff) = b_hi[(size_t)(brow0 + r) * 16 + c16];
        *(uint4*)(smem + SM_B_LO + doff) = b_lo[(size_t)(brow0 + r) * 16 + c16];
    }
    __syncthreads();

    float acc[2][8][4];
    #pragma unroll
    for (int mi = 0; mi < 2; mi++)
        #pragma unroll
        for (int ni = 0; ni < 8; ni++)
            #pragma unroll
            for (int q = 0; q < 4; q++) acc[mi][ni][q] = 0.f;

    uint32_t a_off[2];
    #pragma unroll
    for (int mi = 0; mi < 2; mi++)
        a_off[mi] = (uint32_t)((wm * 32 + mi * 16 + (lane & 15)) * PITCH + (lane >> 4) * 16);
    uint32_t b_off[4];
    {
        int grp = lane >> 3, rin = lane & 7;
        int radd = (grp >= 2) ? 8 : 0;
        int koff = (grp & 1) * 16;
        #pragma unroll
        for (int pi = 0; pi < 4; pi++)
            b_off[pi] = (uint32_t)((wn * 64 + pi * 16 + radd + rin) * PITCH + koff);
    }

    uint32_t smA = sbase + SM_A;

    // three passes; before pass 2 (index p==2) the A tile is reloaded with a_lo
    #pragma unroll
    for (int p = 0; p < 3; p++) {
        if (p == 2) {
            __syncthreads();
            #pragma unroll
            for (int i = tid; i < 2048; i += 256) {
                int r = i >> 4, c16 = i & 15;
                int doff = r * PITCH + c16 * 16;
                uint4 vl = make_uint4(0, 0, 0, 0);
                if (row0 + r < M) vl = a_lo[(size_t)(row0 + r) * 16 + c16];
                *(uint4*)(smem + SM_A + doff) = vl;
            }
            __syncthreads();
        }
        uint32_t bbase = sbase + ((p == 1) ? SM_B_LO : SM_B_HI);
        #pragma unroll
        for (int k16 = 0; k16 < 8; k16++) {
            uint32_t kadd = k16 * 32;
            uint32_t afr[2][4];
            #pragma unroll
            for (int mi = 0; mi < 2; mi++)
                ldsm_x4(afr[mi][0], afr[mi][1], afr[mi][2], afr[mi][3],
                        smA + a_off[mi] + kadd);
            uint32_t bfr[8][2];
            #pragma unroll
            for (int pi = 0; pi < 4; pi++) {
                uint32_t r0, r1, r2, r3;
                ldsm_x4(r0, r1, r2, r3, bbase + b_off[pi] + kadd);
                bfr[pi * 2][0] = r0; bfr[pi * 2][1] = r1;
                bfr[pi * 2 + 1][0] = r2; bfr[pi * 2 + 1][1] = r3;
            }
            #pragma unroll
            for (int ni = 0; ni < 8; ni++) {
                mma16816(acc[0][ni], afr[0], bfr[ni]);
                mma16816(acc[1][ni], afr[1], bfr[ni]);
            }
        }
    }

    // ---- epilogue ----
    float* O = half ? g_z : g_y;
    #pragma unroll
    for (int mi = 0; mi < 2; mi++) {
        int r0 = row0 + wm * 32 + mi * 16 + (lane >> 2);
        #pragma unroll
        for (int ni = 0; ni < 8; ni++) {
            int c = wn * 64 + ni * 8 + (lane & 3) * 2;
            float bx = 0.f, by = 0.f;
            if (half) { bx = bias[c]; by = bias[c + 1]; }
            if (r0 < M) {
                float2 v = make_float2(acc[mi][ni][0] + bx, acc[mi][ni][1] + by);
                *(float2*)&O[(size_t)r0 * HID + c] = v;
            }
            if (r0 + 8 < M) {
                float2 v = make_float2(acc[mi][ni][2] + bx, acc[mi][ni][3] + by);
                *(float2*)&O[(size_t)(r0 + 8) * HID + c] = v;
            }
        }
    }
}

// ---------------- gather-mean: Z[d] += mean_{s in N(d)} Y[s] ----------------
__global__ void aggregate_kernel(int N) {
    int d = blockIdx.x * 8 + (threadIdx.x >> 5);
    int lane = threadIdx.x & 31;
    if (d >= N) return;
    int s0 = g_row_start[d];
    int s1 = g_row_start[d + 1];
    int deg = s1 - s0;
    float inv = 1.0f / (float)(deg > 1 ? deg : 1);

    float4 acc = make_float4(0.f, 0.f, 0.f, 0.f);
    int j = s0;
    for (; j + 3 < s1; j += 4) {
        int sa = g_esrc[j];
        int sb = g_esrc[j + 1];
        int sc = g_esrc[j + 2];
        int sd = g_esrc[j + 3];
        float4 va = ((const float4*)g_y)[(size_t)sa * 32 + lane];
        float4 vb = ((const float4*)g_y)[(size_t)sb * 32 + lane];
        float4 vc = ((const float4*)g_y)[(size_t)sc * 32 + lane];
        float4 vd = ((const float4*)g_y)[(size_t)sd * 32 + lane];
        acc.x += (va.x + vb.x) + (vc.x + vd.x);
        acc.y += (va.y + vb.y) + (vc.y + vd.y);
        acc.z += (va.z + vb.z) + (vc.z + vd.z);
        acc.w += (va.w + vb.w) + (vc.w + vd.w);
    }
    for (; j < s1; j++) {
        int sa = g_esrc[j];
        float4 va = ((const float4*)g_y)[(size_t)sa * 32 + lane];
        acc.x += va.x; acc.y += va.y; acc.z += va.z; acc.w += va.w;
    }

    float4 z = ((const float4*)g_z)[(size_t)d * 32 + lane];
    z.x = fmaf(acc.x, inv, z.x);
    z.y = fmaf(acc.y, inv, z.y);
    z.z = fmaf(acc.z, inv, z.z);
    z.w = fmaf(acc.w, inv, z.w);
    ((float4*)g_z)[(size_t)d * 32 + lane] = z;
}

// ---------------- BatchNorm stats (per-layer stat buffer) ----------------
__global__ void bn_stats_kernel(int M, int layer) {
    int c = threadIdx.x;
    float s = 0.f, q = 0.f;
    for (int r = blockIdx.x; r < M; r += gridDim.x) {
        float v = g_z[(size_t)r * HID + c];
        s += v;
        q += v * v;
    }
    atomicAdd(&g_stat3[layer][c], s);
    atomicAdd(&g_stat3[layer][HID + c], q);
}

// fused: compute scale/shift per block, h = relu(z*sc+sh), emit bf16 hi/lo;
// write fp32 h only when write_h (last layer, for pooling)
__global__ void norm_relu_kernel(int M, int layer, int write_h,
                                 const float* __restrict__ gamma,
                                 const float* __restrict__ beta) {
    __shared__ float s_scale[HID];
    __shared__ float s_shift[HID];
    int tid = threadIdx.x;
    if (tid < HID) {
        float inv_m = 1.0f / (float)M;
        float mu = g_stat3[layer][tid] * inv_m;
        float var = fmaxf(g_stat3[layer][HID + tid] * inv_m - mu * mu, 0.f);
        float sc = gamma[tid] * rsqrtf(var + EPS);
        s_scale[tid] = sc;
        s_shift[tid] = beta[tid] - mu * sc;
    }
    __syncthreads();

    int idx = blockIdx.x * blockDim.x + tid;   // float4 index
    int total = M * 32;
    if (idx >= total) return;
    int c4 = idx & 31;
    float4 z = ((const float4*)g_z)[idx];
    float4 sc = ((const float4*)s_scale)[c4];
    float4 sh = ((const float4*)s_shift)[c4];
    float4 h;
    h.x = fmaxf(fmaf(z.x, sc.x, sh.x), 0.f);
    h.y = fmaxf(fmaf(z.y, sc.y, sh.y), 0.f);
    h.z = fmaxf(fmaf(z.z, sc.z, sh.z), 0.f);
    h.w = fmaxf(fmaf(z.w, sc.w, sh.w), 0.f);
    if (write_h) ((float4*)g_h)[idx] = h;

    __nv_bfloat16 hx = __float2bfloat16(h.x);
    __nv_bfloat16 hy = __float2bfloat16(h.y);
    __nv_bfloat16 hz = __float2bfloat16(h.z);
    __nv_bfloat16 hw = __float2bfloat16(h.w);
    __nv_bfloat162* phi = (__nv_bfloat162*)&g_ah_hi[(size_t)idx * 4];
    phi[0] = __nv_bfloat162(hx, hy);
    phi[1] = __nv_bfloat162(hz, hw);
    __nv_bfloat162* plo = (__nv_bfloat162*)&g_ah_lo[(size_t)idx * 4];
    plo[0] = __nv_bfloat162(__float2bfloat16(h.x - __bfloat162float(hx)),
                            __float2bfloat16(h.y - __bfloat162float(hy)));
    plo[1] = __nv_bfloat162(__float2bfloat16(h.z - __bfloat162float(hz)),
                            __float2bfloat16(h.w - __bfloat162float(hw)));
}

// ---------------- global mean pool (segmented, batch sorted) ----------------
__global__ void pool_kernel(int G) {
    int g = blockIdx.x;
    int c = threadIdx.x;
    if (g >= G) return;
    int r0 = g_gstart[g];
    int r1 = g_gstart[g + 1];
    float s = 0.f;
    for (int r = r0; r < r1; r++) s += g_h[(size_t)r * HID + c];
    int cnt = r1 - r0;
    g_pooled[(size_t)g * HID + c] = s / (float)(cnt > 1 ? cnt : 1);
}

// ---------------- MLP head ----------------
__global__ void head_kernel(const float* __restrict__ Wh1,
                            const float* __restrict__ bh1,
                            const float* __restrict__ Wh2,
                            const float* __restrict__ bh2,
                            float* __restrict__ out, int G)
{
    int g = blockIdx.x;
    int t = threadIdx.x;
    if (g >= G) return;
    float acc = bh1[t];
    #pragma unroll 8
    for (int k = 0; k < HID; k++)
        acc = fmaf(g_pooled[(size_t)g * HID + k], Wh1[k * HIDH + t], acc);
    float v = fmaxf(acc, 0.f) * Wh2[t];
    #pragma unroll
    for (int off = 16; off; off >>= 1)
        v += __shfl_down_sync(0xffffffff, v, off);
    __shared__ float sred[2];
    if ((t & 31) == 0) sred[t >> 5] = v;
    __syncthreads();
    if (t == 0) out[g] = sred[0] + sred[1] + bh2[0];
}

// ---------------- launch ----------------
extern "C" void kernel_launch(void* const* d_in, const int* in_sizes, int n_in,
                              void* d_out, int out_size) {
    const float* x     = (const float*)d_in[0];
    const void*  ei    = d_in[1];
    const void*  batch = d_in[2];

    const float* W_n0 = (const float*)d_in[3];
    const float* b0   = (const float*)d_in[4];
    const float* W_r0 = (const float*)d_in[5];
    const float* g0   = (const float*)d_in[6];
    const float* be0  = (const float*)d_in[7];

    const float* W_n1 = (const float*)d_in[8];
    const float* b1   = (const float*)d_in[9];
    const float* W_r1 = (const float*)d_in[10];
    const float* g1   = (const float*)d_in[11];
    const float* be1  = (const float*)d_in[12];

    const float* W_n2 = (const float*)d_in[13];
    const float* b2   = (const float*)d_in[14];
    const float* W_r2 = (const float*)d_in[15];
    const float* g2   = (const float*)d_in[16];
    const float* be2  = (const float*)d_in[17];

    const float* Wh1 = (const float*)d_in[18];
    const float* bh1 = (const float*)d_in[19];
    const float* Wh2 = (const float*)d_in[20];
    const float* bh2 = (const float*)d_in[21];

    float* out = (float*)d_out;

    const int N = in_sizes[2];
    const int E = in_sizes[1] / 2;
    const int G = out_size;
    const int IN_CH = in_sizes[0] / N;

    cudaFuncSetAttribute(gemm_mma_kernel, cudaFuncAttributeMaxDynamicSharedMemorySize,
                         SM_TOTAL);

    // ---- prep: flag/zero, detect dtype, CSR, segments ----
    prep0_kernel<<<(N + 255) / 256, 256>>>(N);
    detect_kernel<<<8, 256>>>(ei, in_sizes[1]);
    int nscan = (N + SCAN_B - 1) / SCAN_B;
    count_edges_kernel<<<(E + 255) / 256, 256>>>(ei, E);
    scan1_kernel<<<nscan, SCAN_B>>>(N);
    scan2_kernel<<<1, 32>>>(nscan);
    scan3_kernel<<<(N + 255) / 256, 256>>>(N, E);
    fill_edges_kernel<<<(E + 255) / 256, 256>>>(ei, E);
    gstart_kernel<<<(N + 256) / 256, 256>>>(batch, N, G);

    // ---- bf16 split preprocessing ----
    convert_x_kernel<<<(N * KPAD + 255) / 256, 256>>>(x, N, IN_CH);
    {
        dim3 wgrid((256 * KPAD + 255) / 256, 3);
        prep_weights_kernel<<<wgrid, 256>>>(W_n0, W_r0, W_n1, W_r1, W_n2, W_r2, IN_CH);
    }

    dim3 gemm_grid((N + 127) / 128, 2);
    int agg_blocks  = (N + 7) / 8;
    int norm_blocks = (N * 32 + 255) / 256;

    const float* bb[3] = {b0, b1, b2};
    const float* gg[3] = {g0, g1, g2};
    const float* be[3] = {be0, be1, be2};

    for (int l = 0; l < 3; l++) {
        const uint4* ahi;
        const uint4* alo;
        const uint4* bhi;
        const uint4* blo;
        void* p;
        cudaGetSymbolAddress(&p, (l == 0) ? g_ax_hi : g_ah_hi); ahi = (const uint4*)p;
        cudaGetSymbolAddress(&p, (l == 0) ? g_ax_lo : g_ah_lo); alo = (const uint4*)p;
        cudaGetSymbolAddress(&p, g_bw_hi); bhi = (const uint4*)p + (size_t)l * (256 * KPAD / 8);
        cudaGetSymbolAddress(&p, g_bw_lo); blo = (const uint4*)p + (size_t)l * (256 * KPAD / 8);

        gemm_mma_kernel<<<gemm_grid, 256, SM_TOTAL>>>(ahi, alo, bhi, blo, bb[l], N);
        aggregate_kernel<<<agg_blocks, 256>>>(N);
        bn_stats_kernel<<<1024, HID>>>(N, l);
        norm_relu_kernel<<<norm_blocks, 256>>>(N, l, (l == 2) ? 1 : 0, gg[l], be[l]);
    }

    pool_kernel<<<G, HID>>>(G);
    head_kernel<<<G, HIDH>>>(Wh1, bh1, Wh2, bh2, out, G);
}

// round 10
// speedup vs baseline: 1.0752x; 1.0229x over previous
#include <cuda_runtime.h>
#include <cuda_bf16.h>
#include <cuda_fp16.h>
#include <cstdint>

// ---------------- problem constants ----------------
#define N_NODES_MAX 50000
#define N_EDGES_MAX 800000
#define N_GRAPHS_MAX 1000
#define HID 128
#define HIDH 64
#define KPAD 128
#define EPS 1e-5f
#define SCAN_B 1024
#define MAX_BLOCKS ((N_NODES_MAX + SCAN_B - 1) / SCAN_B)

// ---------------- scratch (device globals, allocation-free) ----------------
__device__ __align__(16) __half g_yh[N_NODES_MAX * HID];    // h @ W_n (fp16)
__device__ __align__(16) float g_z[N_NODES_MAX * HID];
__device__ __align__(16) float g_h[N_NODES_MAX * HID];
__device__ __align__(16) __nv_bfloat16 g_ax_hi[N_NODES_MAX * KPAD];
__device__ __align__(16) __nv_bfloat16 g_ax_lo[N_NODES_MAX * KPAD];
__device__ __align__(16) __nv_bfloat16 g_ah_hi[N_NODES_MAX * KPAD];
__device__ __align__(16) __nv_bfloat16 g_ah_lo[N_NODES_MAX * KPAD];
__device__ __align__(16) __nv_bfloat16 g_bw_hi[3][256 * KPAD];   // [Wn|Wr]^T hi, [n][k]
__device__ __align__(16) __nv_bfloat16 g_bw_lo[3][256 * KPAD];
__device__ int   g_is64;
__device__ int   g_indeg[N_NODES_MAX];
__device__ int   g_rowexcl[N_NODES_MAX];
__device__ int   g_bsum[MAX_BLOCKS];
__device__ int   g_bsumex[MAX_BLOCKS];
__device__ int   g_row_start[N_NODES_MAX + 1];
__device__ int   g_epos[N_NODES_MAX];
__device__ int   g_esrc[N_EDGES_MAX];
__device__ int   g_gstart[N_GRAPHS_MAX + 1];
__device__ float g_statp[3][2 * HID][32];    // padded: one 128B line per stat
__device__ __align__(16) float g_pooled[N_GRAPHS_MAX * HID];

// ---------------- index-width handling ----------------
__device__ __forceinline__ int ld_idx(const void* p, long long i, int is64) {
    if (is64) return (int)((const long long*)p)[i];
    return ((const int*)p)[i];
}

// ---------------- combined prep: flag init + zero indeg + zero stats -------
__global__ void prep0_kernel(int N) {
    int i = blockIdx.x * blockDim.x + threadIdx.x;
    if (i == 0) g_is64 = 1;
    if (i < N) g_indeg[i] = 0;
    if (i < 3 * 2 * HID) g_statp[i / (2 * HID)][i % (2 * HID)][0] = 0.f;
}

__global__ void detect_kernel(const void* ei, int n_i32) {
    int i = blockIdx.x * blockDim.x + threadIdx.x;
    int idx = 2 * i + 1;
    if (idx < n_i32 && ((const int*)ei)[idx] != 0) g_is64 = 0;
}

// ---------------- CSR build ----------------
__global__ void count_edges_kernel(const void* __restrict__ ei, int E) {
    int e = blockIdx.x * blockDim.x + threadIdx.x;
    if (e >= E) return;
    atomicAdd(&g_indeg[ld_idx(ei, (long long)E + e, g_is64)], 1);
}

__global__ void scan1_kernel(int N) {
    __shared__ int sh[SCAN_B];
    int i = blockIdx.x * SCAN_B + threadIdx.x;
    int v = (i < N) ? g_indeg[i] : 0;
    sh[threadIdx.x] = v;
    __syncthreads();
    #pragma unroll
    for (int off = 1; off < SCAN_B; off <<= 1) {
        int t = 0;
        if (threadIdx.x >= off) t = sh[threadIdx.x - off];
        __syncthreads();
        sh[threadIdx.x] += t;
        __syncthreads();
    }
    if (i < N) g_rowexcl[i] = sh[threadIdx.x] - v;
    if (threadIdx.x == SCAN_B - 1) g_bsum[blockIdx.x] = sh[SCAN_B - 1];
}

__global__ void scan2_kernel(int nblocks) {
    if (threadIdx.x == 0) {
        int run = 0;
        for (int b = 0; b < nblocks; b++) { int t = g_bsum[b]; g_bsumex[b] = run; run += t; }
    }
}

__global__ void scan3_kernel(int N, int E) {
    int i = blockIdx.x * blockDim.x + threadIdx.x;
    if (i < N) {
        int v = g_rowexcl[i] + g_bsumex[i >> 10];
        g_row_start[i] = v;
        g_epos[i] = v;
    }
    if (i == 0) g_row_start[N] = E;
}

__global__ void fill_edges_kernel(const void* __restrict__ ei, int E) {
    int e = blockIdx.x * blockDim.x + threadIdx.x;
    if (e >= E) return;
    int is64 = g_is64;
    int s = ld_idx(ei, e, is64);
    int d = ld_idx(ei, (long long)E + e, is64);
    g_esrc[atomicAdd(&g_epos[d], 1)] = s;
}

__global__ void gstart_kernel(const void* __restrict__ batch, int N, int G) {
    int i = blockIdx.x * blockDim.x + threadIdx.x;
    if (i > N) return;
    int is64 = g_is64;
    int cur  = (i == N) ? G : ld_idx(batch, i, is64);
    int prev = (i == 0) ? -1 : ld_idx(batch, i - 1, is64);
    for (int g = prev + 1; g <= cur && g <= G; g++) g_gstart[g] = i;
}

// ---------------- bf16 split conversions ----------------
__global__ void convert_x_kernel(const float* __restrict__ x, int N, int IN_CH) {
    int idx = blockIdx.x * blockDim.x + threadIdx.x;
    if (idx >= N * KPAD) return;
    int r = idx >> 7, k = idx & 127;
    float v = (k < IN_CH) ? x[(size_t)r * IN_CH + k] : 0.f;
    __nv_bfloat16 hi = __float2bfloat16(v);
    g_ax_hi[idx] = hi;
    g_ax_lo[idx] = __float2bfloat16(v - __bfloat162float(hi));
}

// one launch for all 3 layers: blockIdx.y = layer
__global__ void prep_weights_kernel(const float* __restrict__ Wn0, const float* __restrict__ Wr0,
                                    const float* __restrict__ Wn1, const float* __restrict__ Wr1,
                                    const float* __restrict__ Wn2, const float* __restrict__ Wr2,
                                    int IN_CH) {
    int idx = blockIdx.x * blockDim.x + threadIdx.x;
    if (idx >= 256 * KPAD) return;
    int layer = blockIdx.y;
    const float* Wn = (layer == 0) ? Wn0 : (layer == 1) ? Wn1 : Wn2;
    const float* Wr = (layer == 0) ? Wr0 : (layer == 1) ? Wr1 : Wr2;
    int K_real = (layer == 0) ? IN_CH : HID;
    int n = idx >> 7, k = idx & 127;
    float v = 0.f;
    if (k < K_real) v = (n < HID) ? Wn[(size_t)k * HID + n] : Wr[(size_t)k * HID + (n - HID)];
    __nv_bfloat16 hi = __float2bfloat16(v);
    g_bw_hi[layer][idx] = hi;
    g_bw_lo[layer][idx] = __float2bfloat16(v - __bfloat162float(hi));
}

// ---------------- mma.sync dual GEMM (split halves, 3-tile SMEM) -----------
#define PITCH 272
#define A_TILE (128 * PITCH)            // 34816
#define SM_A    0
#define SM_B_HI A_TILE
#define SM_B_LO (2 * A_TILE)
#define SM_TOTAL (3 * A_TILE)           // 104448

__device__ __forceinline__ uint32_t smem_u32(const void* p) {
    uint32_t a;
    asm("{ .reg .u64 t; cvta.to.shared.u64 t, %1; cvt.u32.u64 %0, t; }" : "=r"(a) : "l"(p));
    return a;
}

__device__ __forceinline__ void ldsm_x4(uint32_t& r0, uint32_t& r1, uint32_t& r2, uint32_t& r3,
                                        uint32_t addr) {
    asm volatile("ldmatrix.sync.aligned.m8n8.x4.shared.b16 {%0,%1,%2,%3}, [%4];"
                 : "=r"(r0), "=r"(r1), "=r"(r2), "=r"(r3) : "r"(addr));
}

__device__ __forceinline__ void mma16816(float* c, const uint32_t* a, const uint32_t* b) {
    asm volatile(
        "mma.sync.aligned.m16n8k16.row.col.f32.bf16.bf16.f32 "
        "{%0,%1,%2,%3}, {%4,%5,%6,%7}, {%8,%9}, {%0,%1,%2,%3};"
        : "+f"(c[0]), "+f"(c[1]), "+f"(c[2]), "+f"(c[3])
        : "r"(a[0]), "r"(a[1]), "r"(a[2]), "r"(a[3]), "r"(b[0]), "r"(b[1]));
}

__global__ __launch_bounds__(256, 2)
void gemm_mma_kernel(const uint4* __restrict__ a_hi, const uint4* __restrict__ a_lo,
                     const uint4* __restrict__ b_hi, const uint4* __restrict__ b_lo,
                     const float* __restrict__ bias, int M)
{
    extern __shared__ char smem[];
    uint32_t sbase = smem_u32(smem);

    int tid = threadIdx.x;
    int lane = tid & 31;
    int wid = tid >> 5;
    int wm = wid & 3;
    int wn = wid >> 2;
    int row0 = blockIdx.x * 128;
    int half = blockIdx.y;
    int brow0 = half * 128;

    // ---- load A_hi + both B tiles ----
    #pragma unroll
    for (int i = tid; i < 2048; i += 256) {
        int r = i >> 4, c16 = i & 15;
        int doff = r * PITCH + c16 * 16;
        uint4 vh = make_uint4(0, 0, 0, 0);
        if (row0 + r < M) vh = a_hi[(size_t)(row0 + r) * 16 + c16];
        *(uint4*)(smem + SM_A + doff) = vh;
        *(uint4*)(smem + SM_B_HI + doff) = b_hi[(size_t)(brow0 + r) * 16 + c16];
        *(uint4*)(smem + SM_B_LO + doff) = b_lo[(size_t)(brow0 + r) * 16 + c16];
    }
    __syncthreads();

    float acc[2][8][4];
    #pragma unroll
    for (int mi = 0; mi < 2; mi++)
        #pragma unroll
        for (int ni = 0; ni < 8; ni++)
            #pragma unroll
            for (int q = 0; q < 4; q++) acc[mi][ni][q] = 0.f;

    uint32_t a_off[2];
    #pragma unroll
    for (int mi = 0; mi < 2; mi++)
        a_off[mi] = (uint32_t)((wm * 32 + mi * 16 + (lane & 15)) * PITCH + (lane >> 4) * 16);
    uint32_t b_off[4];
    {
        int grp = lane >> 3, rin = lane & 7;
        int radd = (grp >= 2) ? 8 : 0;
        int koff = (grp & 1) * 16;
        #pragma unroll
        for (int pi = 0; pi < 4; pi++)
            b_off[pi] = (uint32_t)((wn * 64 + pi * 16 + radd + rin) * PITCH + koff);
    }

    uint32_t smA = sbase + SM_A;

    #pragma unroll
    for (int p = 0; p < 3; p++) {
        if (p == 2) {
            __syncthreads();
            #pragma unroll
            for (int i = tid; i < 2048; i += 256) {
                int r = i >> 4, c16 = i & 15;
                int doff = r * PITCH + c16 * 16;
                uint4 vl = make_uint4(0, 0, 0, 0);
                if (row0 + r < M) vl = a_lo[(size_t)(row0 + r) * 16 + c16];
                *(uint4*)(smem + SM_A + doff) = vl;
            }
            __syncthreads();
        }
        uint32_t bbase = sbase + ((p == 1) ? SM_B_LO : SM_B_HI);
        #pragma unroll
        for (int k16 = 0; k16 < 8; k16++) {
            uint32_t kadd = k16 * 32;
            uint32_t afr[2][4];
            #pragma unroll
            for (int mi = 0; mi < 2; mi++)
                ldsm_x4(afr[mi][0], afr[mi][1], afr[mi][2], afr[mi][3],
                        smA + a_off[mi] + kadd);
            uint32_t bfr[8][2];
            #pragma unroll
            for (int pi = 0; pi < 4; pi++) {
                uint32_t r0, r1, r2, r3;
                ldsm_x4(r0, r1, r2, r3, bbase + b_off[pi] + kadd);
                bfr[pi * 2][0] = r0; bfr[pi * 2][1] = r1;
                bfr[pi * 2 + 1][0] = r2; bfr[pi * 2 + 1][1] = r3;
            }
            #pragma unroll
            for (int ni = 0; ni < 8; ni++) {
                mma16816(acc[0][ni], afr[0], bfr[ni]);
                mma16816(acc[1][ni], afr[1], bfr[ni]);
            }
        }
    }

    // ---- epilogue: half 0 -> g_yh (fp16), half 1 -> g_z (fp32 + bias) ----
    #pragma unroll
    for (int mi = 0; mi < 2; mi++) {
        int r0 = row0 + wm * 32 + mi * 16 + (lane >> 2);
        #pragma unroll
        for (int ni = 0; ni < 8; ni++) {
            int c = wn * 64 + ni * 8 + (lane & 3) * 2;
            if (half) {
                float bx = bias[c], by = bias[c + 1];
                if (r0 < M) {
                    float2 v = make_float2(acc[mi][ni][0] + bx, acc[mi][ni][1] + by);
                    *(float2*)&g_z[(size_t)r0 * HID + c] = v;
                }
                if (r0 + 8 < M) {
                    float2 v = make_float2(acc[mi][ni][2] + bx, acc[mi][ni][3] + by);
                    *(float2*)&g_z[(size_t)(r0 + 8) * HID + c] = v;
                }
            } else {
                if (r0 < M) {
                    __half2 v = __floats2half2_rn(acc[mi][ni][0], acc[mi][ni][1]);
                    *(__half2*)&g_yh[(size_t)r0 * HID + c] = v;
                }
                if (r0 + 8 < M) {
                    __half2 v = __floats2half2_rn(acc[mi][ni][2], acc[mi][ni][3]);
                    *(__half2*)&g_yh[(size_t)(r0 + 8) * HID + c] = v;
                }
            }
        }
    }
}

// ---------------- gather-mean + fused BN stats ------------------------------
// Z[d] += mean_{s in N(d)} Y[s]; block-reduce per-channel sum/sumsq -> g_statp
__global__ void aggregate_kernel(int N, int layer) {
    __shared__ float sh_s[8][132];
    __shared__ float sh_q[8][132];
    int wid = threadIdx.x >> 5;
    int lane = threadIdx.x & 31;
    int d = blockIdx.x * 8 + wid;

    float4 z = make_float4(0.f, 0.f, 0.f, 0.f);
    if (d < N) {
        int s0 = g_row_start[d];
        int s1 = g_row_start[d + 1];
        int deg = s1 - s0;
        float inv = 1.0f / (float)(deg > 1 ? deg : 1);
        const uint2* Y = (const uint2*)g_yh;

        float4 acc = make_float4(0.f, 0.f, 0.f, 0.f);
        int j = s0;
        for (; j + 3 < s1; j += 4) {
            uint2 ua = Y[(size_t)g_esrc[j] * 32 + lane];
            uint2 ub = Y[(size_t)g_esrc[j + 1] * 32 + lane];
            uint2 uc = Y[(size_t)g_esrc[j + 2] * 32 + lane];
            uint2 ud = Y[(size_t)g_esrc[j + 3] * 32 + lane];
            float2 a0 = __half22float2(*(__half2*)&ua.x), a1 = __half22float2(*(__half2*)&ua.y);
            float2 b0 = __half22float2(*(__half2*)&ub.x), b1 = __half22float2(*(__half2*)&ub.y);
            float2 c0 = __half22float2(*(__half2*)&uc.x), c1 = __half22float2(*(__half2*)&uc.y);
            float2 d0 = __half22float2(*(__half2*)&ud.x), d1 = __half22float2(*(__half2*)&ud.y);
            acc.x += (a0.x + b0.x) + (c0.x + d0.x);
            acc.y += (a0.y + b0.y) + (c0.y + d0.y);
            acc.z += (a1.x + b1.x) + (c1.x + d1.x);
            acc.w += (a1.y + b1.y) + (c1.y + d1.y);
        }
        for (; j < s1; j++) {
            uint2 ua = Y[(size_t)g_esrc[j] * 32 + lane];
            float2 a0 = __half22float2(*(__half2*)&ua.x), a1 = __half22float2(*(__half2*)&ua.y);
            acc.x += a0.x; acc.y += a0.y; acc.z += a1.x; acc.w += a1.y;
        }

        z = ((const float4*)g_z)[(size_t)d * 32 + lane];
        z.x = fmaf(acc.x, inv, z.x);
        z.y = fmaf(acc.y, inv, z.y);
        z.z = fmaf(acc.z, inv, z.z);
        z.w = fmaf(acc.w, inv, z.w);
        ((float4*)g_z)[(size_t)d * 32 + lane] = z;
    }

    // fused BN stats: per-block channel reduction, one RED per channel/stat
    float4 q = make_float4(z.x * z.x, z.y * z.y, z.z * z.z, z.w * z.w);
    *(float4*)&sh_s[wid][4 * lane] = z;
    *(float4*)&sh_q[wid][4 * lane] = q;
    __syncthreads();
    int t = threadIdx.x;
    if (t < HID) {
        float s = 0.f;
        #pragma unroll
        for (int w = 0; w < 8; w++) s += sh_s[w][t];
        atomicAdd(&g_statp[layer][t][0], s);
    } else {
        int c = t - HID;
        float s = 0.f;
        #pragma unroll
        for (int w = 0; w < 8; w++) s += sh_q[w][c];
        atomicAdd(&g_statp[layer][HID + c][0], s);
    }
}

// fused: compute scale/shift per block, h = relu(z*sc+sh), emit bf16 hi/lo;
// write fp32 h only when write_h (last layer, for pooling)
__global__ void norm_relu_kernel(int M, int layer, int write_h,
                                 const float* __restrict__ gamma,
                                 const float* __restrict__ beta) {
    __shared__ float s_scale[HID];
    __shared__ float s_shift[HID];
    int tid = threadIdx.x;
    if (tid < HID) {
        float inv_m = 1.0f / (float)M;
        float mu = g_statp[layer][tid][0] * inv_m;
        float var = fmaxf(g_statp[layer][HID + tid][0] * inv_m - mu * mu, 0.f);
        float sc = gamma[tid] * rsqrtf(var + EPS);
        s_scale[tid] = sc;
        s_shift[tid] = beta[tid] - mu * sc;
    }
    __syncthreads();

    int idx = blockIdx.x * blockDim.x + tid;   // float4 index
    int total = M * 32;
    if (idx >= total) return;
    int c4 = idx & 31;
    float4 z = ((const float4*)g_z)[idx];
    float4 sc = ((const float4*)s_scale)[c4];
    float4 sh = ((const float4*)s_shift)[c4];
    float4 h;
    h.x = fmaxf(fmaf(z.x, sc.x, sh.x), 0.f);
    h.y = fmaxf(fmaf(z.y, sc.y, sh.y), 0.f);
    h.z = fmaxf(fmaf(z.z, sc.z, sh.z), 0.f);
    h.w = fmaxf(fmaf(z.w, sc.w, sh.w), 0.f);
    if (write_h) ((float4*)g_h)[idx] = h;

    __nv_bfloat16 hx = __float2bfloat16(h.x);
    __nv_bfloat16 hy = __float2bfloat16(h.y);
    __nv_bfloat16 hz = __float2bfloat16(h.z);
    __nv_bfloat16 hw = __float2bfloat16(h.w);
    __nv_bfloat162* phi = (__nv_bfloat162*)&g_ah_hi[(size_t)idx * 4];
    phi[0] = __nv_bfloat162(hx, hy);
    phi[1] = __nv_bfloat162(hz, hw);
    __nv_bfloat162* plo = (__nv_bfloat162*)&g_ah_lo[(size_t)idx * 4];
    plo[0] = __nv_bfloat162(__float2bfloat16(h.x - __bfloat162float(hx)),
                            __float2bfloat16(h.y - __bfloat162float(hy)));
    plo[1] = __nv_bfloat162(__float2bfloat16(h.z - __bfloat162float(hz)),
                            __float2bfloat16(h.w - __bfloat162float(hw)));
}

// ---------------- global mean pool (segmented, batch sorted) ----------------
__global__ void pool_kernel(int G) {
    int g = blockIdx.x;
    int c = threadIdx.x;
    if (g >= G) return;
    int r0 = g_gstart[g];
    int r1 = g_gstart[g + 1];
    float s = 0.f;
    for (int r = r0; r < r1; r++) s += g_h[(size_t)r * HID + c];
    int cnt = r1 - r0;
    g_pooled[(size_t)g * HID + c] = s / (float)(cnt > 1 ? cnt : 1);
}

// ---------------- MLP head ----------------
__global__ void head_kernel(const float* __restrict__ Wh1,
                            const float* __restrict__ bh1,
                            const float* __restrict__ Wh2,
                            const float* __restrict__ bh2,
                            float* __restrict__ out, int G)
{
    int g = blockIdx.x;
    int t = threadIdx.x;
    if (g >= G) return;
    float acc = bh1[t];
    #pragma unroll 8
    for (int k = 0; k < HID; k++)
        acc = fmaf(g_pooled[(size_t)g * HID + k], Wh1[k * HIDH + t], acc);
    float v = fmaxf(acc, 0.f) * Wh2[t];
    #pragma unroll
    for (int off = 16; off; off >>= 1)
        v += __shfl_down_sync(0xffffffff, v, off);
    __shared__ float sred[2];
    if ((t & 31) == 0) sred[t >> 5] = v;
    __syncthreads();
    if (t == 0) out[g] = sred[0] + sred[1] + bh2[0];
}

// ---------------- launch ----------------
extern "C" void kernel_launch(void* const* d_in, const int* in_sizes, int n_in,
                              void* d_out, int out_size) {
    const float* x     = (const float*)d_in[0];
    const void*  ei    = d_in[1];
    const void*  batch = d_in[2];

    const float* W_n0 = (const float*)d_in[3];
    const float* b0   = (const float*)d_in[4];
    const float* W_r0 = (const float*)d_in[5];
    const float* g0   = (const float*)d_in[6];
    const float* be0  = (const float*)d_in[7];

    const float* W_n1 = (const float*)d_in[8];
    const float* b1   = (const float*)d_in[9];
    const float* W_r1 = (const float*)d_in[10];
    const float* g1   = (const float*)d_in[11];
    const float* be1  = (const float*)d_in[12];

    const float* W_n2 = (const float*)d_in[13];
    const float* b2   = (const float*)d_in[14];
    const float* W_r2 = (const float*)d_in[15];
    const float* g2   = (const float*)d_in[16];
    const float* be2  = (const float*)d_in[17];

    const float* Wh1 = (const float*)d_in[18];
    const float* bh1 = (const float*)d_in[19];
    const float* Wh2 = (const float*)d_in[20];
    const float* bh2 = (const float*)d_in[21];

    float* out = (float*)d_out;

    const int N = in_sizes[2];
    const int E = in_sizes[1] / 2;
    const int G = out_size;
    const int IN_CH = in_sizes[0] / N;

    cudaFuncSetAttribute(gemm_mma_kernel, cudaFuncAttributeMaxDynamicSharedMemorySize,
                         SM_TOTAL);

    // ---- prep: flag/zero, detect dtype, CSR, segments ----
    prep0_kernel<<<(N + 255) / 256, 256>>>(N);
    detect_kernel<<<8, 256>>>(ei, in_sizes[1]);
    int nscan = (N + SCAN_B - 1) / SCAN_B;
    count_edges_kernel<<<(E + 255) / 256, 256>>>(ei, E);
    scan1_kernel<<<nscan, SCAN_B>>>(N);
    scan2_kernel<<<1, 32>>>(nscan);
    scan3_kernel<<<(N + 255) / 256, 256>>>(N, E);
    fill_edges_kernel<<<(E + 255) / 256, 256>>>(ei, E);
    gstart_kernel<<<(N + 256) / 256, 256>>>(batch, N, G);

    // ---- bf16 split preprocessing ----
    convert_x_kernel<<<(N * KPAD + 255) / 256, 256>>>(x, N, IN_CH);
    {
        dim3 wgrid((256 * KPAD + 255) / 256, 3);
        prep_weights_kernel<<<wgrid, 256>>>(W_n0, W_r0, W_n1, W_r1, W_n2, W_r2, IN_CH);
    }

    dim3 gemm_grid((N + 127) / 128, 2);
    int agg_blocks  = (N + 7) / 8;
    int norm_blocks = (N * 32 + 255) / 256;

    const float* bb[3] = {b0, b1, b2};
    const float* gg[3] = {g0, g1, g2};
    const float* be[3] = {be0, be1, be2};

    for (int l = 0; l < 3; l++) {
        const uint4* ahi;
        const uint4* alo;
        const uint4* bhi;
        const uint4* blo;
        void* p;
        cudaGetSymbolAddress(&p, (l == 0) ? g_ax_hi : g_ah_hi); ahi = (const uint4*)p;
        cudaGetSymbolAddress(&p, (l == 0) ? g_ax_lo : g_ah_lo); alo = (const uint4*)p;
        cudaGetSymbolAddress(&p, g_bw_hi); bhi = (const uint4*)p + (size_t)l * (256 * KPAD / 8);
        cudaGetSymbolAddress(&p, g_bw_lo); blo = (const uint4*)p + (size_t)l * (256 * KPAD / 8);

        gemm_mma_kernel<<<gemm_grid, 256, SM_TOTAL>>>(ahi, alo, bhi, blo, bb[l], N);
        aggregate_kernel<<<agg_blocks, 256>>>(N, l);
        norm_relu_kernel<<<norm_blocks, 256>>>(N, l, (l == 2) ? 1 : 0, gg[l], be[l]);
    }

    pool_kernel<<<G, HID>>>(G);
    head_kernel<<<G, HIDH>>>(Wh1, bh1, Wh2, bh2, out, G);
}

// round 12
// speedup vs baseline: 1.1272x; 1.0484x over previous
#include <cuda_runtime.h>
#include <cuda_bf16.h>
#include <cuda_fp16.h>
#include <cstdint>

// ---------------- problem constants ----------------
#define N_NODES_MAX 50000
#define N_EDGES_MAX 800000
#define N_GRAPHS_MAX 1000
#define HID 128
#define HIDH 64
#define KPAD 128
#define EPS 1e-5f
#define SCAN_B 1024
#define MAX_BLOCKS ((N_NODES_MAX + SCAN_B - 1) / SCAN_B)

// ---------------- scratch (device globals, allocation-free) ----------------
__device__ __align__(16) __half g_yh[N_NODES_MAX * HID];    // h @ W_n (fp16)
__device__ __align__(16) __half g_zh[N_NODES_MAX * HID];    // h @ W_r + b + agg (fp16)
__device__ __align__(16) float g_h[N_NODES_MAX * HID];
__device__ __align__(16) __nv_bfloat16 g_ax_hi[N_NODES_MAX * KPAD];
__device__ __align__(16) __nv_bfloat16 g_ax_lo[N_NODES_MAX * KPAD];
__device__ __align__(16) __nv_bfloat16 g_ah_hi[N_NODES_MAX * KPAD];
__device__ __align__(16) __nv_bfloat16 g_ah_lo[N_NODES_MAX * KPAD];
__device__ __align__(16) __nv_bfloat16 g_bw_hi[3][256 * KPAD];   // [Wn|Wr]^T hi, [n][k]
__device__ __align__(16) __nv_bfloat16 g_bw_lo[3][256 * KPAD];
__device__ int   g_is64;
__device__ int   g_indeg[N_NODES_MAX];
__device__ int   g_rowexcl[N_NODES_MAX];
__device__ int   g_bsum[MAX_BLOCKS];
__device__ int   g_bsumex[MAX_BLOCKS];
__device__ int   g_row_start[N_NODES_MAX + 1];
__device__ int   g_epos[N_NODES_MAX];
__device__ int   g_esrc[N_EDGES_MAX];
__device__ int   g_gstart[N_GRAPHS_MAX + 1];
__device__ float g_statp[3][2 * HID][32];    // padded: one 128B line per stat
__device__ __align__(16) float g_pooled[N_GRAPHS_MAX * HID];

// ---------------- index-width handling ----------------
__device__ __forceinline__ int ld_idx(const void* p, long long i, int is64) {
    if (is64) return (int)((const long long*)p)[i];
    return ((const int*)p)[i];
}

// ---------------- combined prep: flag init + zero indeg + zero stats -------
__global__ void prep0_kernel(int N) {
    int i = blockIdx.x * blockDim.x + threadIdx.x;
    if (i == 0) g_is64 = 1;
    if (i < N) g_indeg[i] = 0;
    if (i < 3 * 2 * HID) g_statp[i / (2 * HID)][i % (2 * HID)][0] = 0.f;
}

__global__ void detect_kernel(const void* ei, int n_i32) {
    int i = blockIdx.x * blockDim.x + threadIdx.x;
    int idx = 2 * i + 1;
    if (idx < n_i32 && ((const int*)ei)[idx] != 0) g_is64 = 0;
}

// ---------------- CSR build ----------------
__global__ void count_edges_kernel(const void* __restrict__ ei, int E) {
    int e = blockIdx.x * blockDim.x + threadIdx.x;
    if (e >= E) return;
    atomicAdd(&g_indeg[ld_idx(ei, (long long)E + e, g_is64)], 1);
}

__global__ void scan1_kernel(int N) {
    __shared__ int sh[SCAN_B];
    int i = blockIdx.x * SCAN_B + threadIdx.x;
    int v = (i < N) ? g_indeg[i] : 0;
    sh[threadIdx.x] = v;
    __syncthreads();
    #pragma unroll
    for (int off = 1; off < SCAN_B; off <<= 1) {
        int t = 0;
        if (threadIdx.x >= off) t = sh[threadIdx.x - off];
        __syncthreads();
        sh[threadIdx.x] += t;
        __syncthreads();
    }
    if (i < N) g_rowexcl[i] = sh[threadIdx.x] - v;
    if (threadIdx.x == SCAN_B - 1) g_bsum[blockIdx.x] = sh[SCAN_B - 1];
}

__global__ void scan2_kernel(int nblocks) {
    if (threadIdx.x == 0) {
        int run = 0;
        for (int b = 0; b < nblocks; b++) { int t = g_bsum[b]; g_bsumex[b] = run; run += t; }
    }
}

__global__ void scan3_kernel(int N, int E) {
    int i = blockIdx.x * blockDim.x + threadIdx.x;
    if (i < N) {
        int v = g_rowexcl[i] + g_bsumex[i >> 10];
        g_row_start[i] = v;
        g_epos[i] = v;
    }
    if (i == 0) g_row_start[N] = E;
}

__global__ void fill_edges_kernel(const void* __restrict__ ei, int E) {
    int e = blockIdx.x * blockDim.x + threadIdx.x;
    if (e >= E) return;
    int is64 = g_is64;
    int s = ld_idx(ei, e, is64);
    int d = ld_idx(ei, (long long)E + e, is64);
    g_esrc[atomicAdd(&g_epos[d], 1)] = s;
}

__global__ void gstart_kernel(const void* __restrict__ batch, int N, int G) {
    int i = blockIdx.x * blockDim.x + threadIdx.x;
    if (i > N) return;
    int is64 = g_is64;
    int cur  = (i == N) ? G : ld_idx(batch, i, is64);
    int prev = (i == 0) ? -1 : ld_idx(batch, i - 1, is64);
    for (int g = prev + 1; g <= cur && g <= G; g++) g_gstart[g] = i;
}

// ---------------- bf16 split conversions ----------------
__global__ void convert_x_kernel(const float* __restrict__ x, int N, int IN_CH) {
    int idx = blockIdx.x * blockDim.x + threadIdx.x;
    if (idx >= N * KPAD) return;
    int r = idx >> 7, k = idx & 127;
    float v = (k < IN_CH) ? x[(size_t)r * IN_CH + k] : 0.f;
    __nv_bfloat16 hi = __float2bfloat16(v);
    g_ax_hi[idx] = hi;
    g_ax_lo[idx] = __float2bfloat16(v - __bfloat162float(hi));
}

// one launch for all 3 layers: blockIdx.y = layer
__global__ void prep_weights_kernel(const float* __restrict__ Wn0, const float* __restrict__ Wr0,
                                    const float* __restrict__ Wn1, const float* __restrict__ Wr1,
                                    const float* __restrict__ Wn2, const float* __restrict__ Wr2,
                                    int IN_CH) {
    int idx = blockIdx.x * blockDim.x + threadIdx.x;
    if (idx >= 256 * KPAD) return;
    int layer = blockIdx.y;
    const float* Wn = (layer == 0) ? Wn0 : (layer == 1) ? Wn1 : Wn2;
    const float* Wr = (layer == 0) ? Wr0 : (layer == 1) ? Wr1 : Wr2;
    int K_real = (layer == 0) ? IN_CH : HID;
    int n = idx >> 7, k = idx & 127;
    float v = 0.f;
    if (k < K_real) v = (n < HID) ? Wn[(size_t)k * HID + n] : Wr[(size_t)k * HID + (n - HID)];
    __nv_bfloat16 hi = __float2bfloat16(v);
    g_bw_hi[layer][idx] = hi;
    g_bw_lo[layer][idx] = __float2bfloat16(v - __bfloat162float(hi));
}

// ---------------- mma.sync dual GEMM (split halves, 3-tile SMEM) -----------
// grid (nb, 2). blockIdx.y: 0 -> g_yh (fp16), 1 -> g_zh (fp16 + bias).
// Passes: p1 = Ahi*Bhi, p2 = Ahi*Blo, [reload A with Alo], p3 = Alo*Bhi.
#define PITCH 272
#define A_TILE (128 * PITCH)            // 34816
#define SM_A    0
#define SM_B_HI A_TILE
#define SM_B_LO (2 * A_TILE)
#define SM_TOTAL (3 * A_TILE)           // 104448

__device__ __forceinline__ uint32_t smem_u32(const void* p) {
    uint32_t a;
    asm("{ .reg .u64 t; cvta.to.shared.u64 t, %1; cvt.u32.u64 %0, t; }" : "=r"(a) : "l"(p));
    return a;
}

__device__ __forceinline__ void ldsm_x4(uint32_t& r0, uint32_t& r1, uint32_t& r2, uint32_t& r3,
                                        uint32_t addr) {
    asm volatile("ldmatrix.sync.aligned.m8n8.x4.shared.b16 {%0,%1,%2,%3}, [%4];"
                 : "=r"(r0), "=r"(r1), "=r"(r2), "=r"(r3) : "r"(addr));
}

__device__ __forceinline__ void mma16816(float* c, const uint32_t* a, const uint32_t* b) {
    asm volatile(
        "mma.sync.aligned.m16n8k16.row.col.f32.bf16.bf16.f32 "
        "{%0,%1,%2,%3}, {%4,%5,%6,%7}, {%8,%9}, {%0,%1,%2,%3};"
        : "+f"(c[0]), "+f"(c[1]), "+f"(c[2]), "+f"(c[3])
        : "r"(a[0]), "r"(a[1]), "r"(a[2]), "r"(a[3]), "r"(b[0]), "r"(b[1]));
}

__global__ __launch_bounds__(256, 2)
void gemm_mma_kernel(const uint4* __restrict__ a_hi, const uint4* __restrict__ a_lo,
                     const uint4* __restrict__ b_hi, const uint4* __restrict__ b_lo,
                     const float* __restrict__ bias, int M)
{
    extern __shared__ char smem[];
    uint32_t sbase = smem_u32(smem);

    int tid = threadIdx.x;
    int lane = tid & 31;
    int wid = tid >> 5;
    int wm = wid & 3;
    int wn = wid >> 2;
    int row0 = blockIdx.x * 128;
    int half = blockIdx.y;
    int brow0 = half * 128;

    // ---- load A_hi + both B tiles ----
    #pragma unroll
    for (int i = tid; i < 2048; i += 256) {
        int r = i >> 4, c16 = i & 15;
        int doff = r * PITCH + c16 * 16;
        uint4 vh = make_uint4(0, 0, 0, 0);
        if (row0 + r < M) vh = a_hi[(size_t)(row0 + r) * 16 + c16];
        *(uint4*)(smem + SM_A + doff) = vh;
        *(uint4*)(smem + SM_B_HI + doff) = b_hi[(size_t)(brow0 + r) * 16 + c16];
        *(uint4*)(smem + SM_B_LO + doff) = b_lo[(size_t)(brow0 + r) * 16 + c16];
    }
    __syncthreads();

    float acc[2][8][4];
    #pragma unroll
    for (int mi = 0; mi < 2; mi++)
        #pragma unroll
        for (int ni = 0; ni < 8; ni++)
            #pragma unroll
            for (int q = 0; q < 4; q++) acc[mi][ni][q] = 0.f;

    uint32_t a_off[2];
    #pragma unroll
    for (int mi = 0; mi < 2; mi++)
        a_off[mi] = (uint32_t)((wm * 32 + mi * 16 + (lane & 15)) * PITCH + (lane >> 4) * 16);
    uint32_t b_off[4];
    {
        int grp = lane >> 3, rin = lane & 7;
        int radd = (grp >= 2) ? 8 : 0;
        int koff = (grp & 1) * 16;
        #pragma unroll
        for (int pi = 0; pi < 4; pi++)
            b_off[pi] = (uint32_t)((wn * 64 + pi * 16 + radd + rin) * PITCH + koff);
    }

    uint32_t smA = sbase + SM_A;

    #pragma unroll
    for (int p = 0; p < 3; p++) {
        if (p == 2) {
            __syncthreads();
            #pragma unroll
            for (int i = tid; i < 2048; i += 256) {
                int r = i >> 4, c16 = i & 15;
                int doff = r * PITCH + c16 * 16;
                uint4 vl = make_uint4(0, 0, 0, 0);
                if (row0 + r < M) vl = a_lo[(size_t)(row0 + r) * 16 + c16];
                *(uint4*)(smem + SM_A + doff) = vl;
            }
            __syncthreads();
        }
        uint32_t bbase = sbase + ((p == 1) ? SM_B_LO : SM_B_HI);
        #pragma unroll
        for (int k16 = 0; k16 < 8; k16++) {
            uint32_t kadd = k16 * 32;
            uint32_t afr[2][4];
            #pragma unroll
            for (int mi = 0; mi < 2; mi++)
                ldsm_x4(afr[mi][0], afr[mi][1], afr[mi][2], afr[mi][3],
                        smA + a_off[mi] + kadd);
            uint32_t bfr[8][2];
            #pragma unroll
            for (int pi = 0; pi < 4; pi++) {
                uint32_t r0, r1, r2, r3;
                ldsm_x4(r0, r1, r2, r3, bbase + b_off[pi] + kadd);
                bfr[pi * 2][0] = r0; bfr[pi * 2][1] = r1;
                bfr[pi * 2 + 1][0] = r2; bfr[pi * 2 + 1][1] = r3;
            }
            #pragma unroll
            for (int ni = 0; ni < 8; ni++) {
                mma16816(acc[0][ni], afr[0], bfr[ni]);
                mma16816(acc[1][ni], afr[1], bfr[ni]);
            }
        }
    }

    // ---- epilogue: half 0 -> g_yh (fp16), half 1 -> g_zh (fp16 + bias) ----
    __half* O = half ? g_zh : g_yh;
    #pragma unroll
    for (int mi = 0; mi < 2; mi++) {
        int r0 = row0 + wm * 32 + mi * 16 + (lane >> 2);
        #pragma unroll
        for (int ni = 0; ni < 8; ni++) {
            int c = wn * 64 + ni * 8 + (lane & 3) * 2;
            float bx = 0.f, by = 0.f;
            if (half) { bx = bias[c]; by = bias[c + 1]; }
            if (r0 < M) {
                __half2 v = __floats2half2_rn(acc[mi][ni][0] + bx, acc[mi][ni][1] + by);
                *(__half2*)&O[(size_t)r0 * HID + c] = v;
            }
            if (r0 + 8 < M) {
                __half2 v = __floats2half2_rn(acc[mi][ni][2] + bx, acc[mi][ni][3] + by);
                *(__half2*)&O[(size_t)(r0 + 8) * HID + c] = v;
            }
        }
    }
}

// ---------------- gather-mean + fused BN stats ------------------------------
__global__ void aggregate_kernel(int N, int layer) {
    __shared__ float sh_s[8][132];
    __shared__ float sh_q[8][132];
    int wid = threadIdx.x >> 5;
    int lane = threadIdx.x & 31;
    int d = blockIdx.x * 8 + wid;

    float4 z = make_float4(0.f, 0.f, 0.f, 0.f);
    if (d < N) {
        int s0 = g_row_start[d];
        int s1 = g_row_start[d + 1];
        int deg = s1 - s0;
        float inv = 1.0f / (float)(deg > 1 ? deg : 1);
        const uint2* Y = (const uint2*)g_yh;

        float4 acc = make_float4(0.f, 0.f, 0.f, 0.f);
        int j = s0;
        for (; j + 3 < s1; j += 4) {
            uint2 ua = Y[(size_t)g_esrc[j] * 32 + lane];
            uint2 ub = Y[(size_t)g_esrc[j + 1] * 32 + lane];
            uint2 uc = Y[(size_t)g_esrc[j + 2] * 32 + lane];
            uint2 ud = Y[(size_t)g_esrc[j + 3] * 32 + lane];
            float2 a0 = __half22float2(*(__half2*)&ua.x), a1 = __half22float2(*(__half2*)&ua.y);
            float2 b0 = __half22float2(*(__half2*)&ub.x), b1 = __half22float2(*(__half2*)&ub.y);
            float2 c0 = __half22float2(*(__half2*)&uc.x), c1 = __half22float2(*(__half2*)&uc.y);
            float2 d0 = __half22float2(*(__half2*)&ud.x), d1 = __half22float2(*(__half2*)&ud.y);
            acc.x += (a0.x + b0.x) + (c0.x + d0.x);
            acc.y += (a0.y + b0.y) + (c0.y + d0.y);
            acc.z += (a1.x + b1.x) + (c1.x + d1.x);
            acc.w += (a1.y + b1.y) + (c1.y + d1.y);
        }
        for (; j < s1; j++) {
            uint2 ua = Y[(size_t)g_esrc[j] * 32 + lane];
            float2 a0 = __half22float2(*(__half2*)&ua.x), a1 = __half22float2(*(__half2*)&ua.y);
            acc.x += a0.x; acc.y += a0.y; acc.z += a1.x; acc.w += a1.y;
        }

        uint2 uz = ((const uint2*)g_zh)[(size_t)d * 32 + lane];
        float2 z01 = __half22float2(*(__half2*)&uz.x);
        float2 z23 = __half22float2(*(__half2*)&uz.y);
        z.x = fmaf(acc.x, inv, z01.x);
        z.y = fmaf(acc.y, inv, z01.y);
        z.z = fmaf(acc.z, inv, z23.x);
        z.w = fmaf(acc.w, inv, z23.y);
        uint2 uo;
        *(__half2*)&uo.x = __floats2half2_rn(z.x, z.y);
        *(__half2*)&uo.y = __floats2half2_rn(z.z, z.w);
        ((uint2*)g_zh)[(size_t)d * 32 + lane] = uo;
    }

    // fused BN stats
    float4 q = make_float4(z.x * z.x, z.y * z.y, z.z * z.z, z.w * z.w);
    *(float4*)&sh_s[wid][4 * lane] = z;
    *(float4*)&sh_q[wid][4 * lane] = q;
    __syncthreads();
    int t = threadIdx.x;
    if (t < HID) {
        float s = 0.f;
        #pragma unroll
        for (int w = 0; w < 8; w++) s += sh_s[w][t];
        atomicAdd(&g_statp[layer][t][0], s);
    } else {
        int c = t - HID;
        float s = 0.f;
        #pragma unroll
        for (int w = 0; w < 8; w++) s += sh_q[w][c];
        atomicAdd(&g_statp[layer][HID + c][0], s);
    }
}

// fused: compute scale/shift per block, h = relu(z*sc+sh), emit bf16 hi/lo;
// write fp32 h only when write_h (last layer, for pooling)
__global__ void norm_relu_kernel(int M, int layer, int write_h,
                                 const float* __restrict__ gamma,
                                 const float* __restrict__ beta) {
    __shared__ float s_scale[HID];
    __shared__ float s_shift[HID];
    int tid = threadIdx.x;
    if (tid < HID) {
        float inv_m = 1.0f / (float)M;
        float mu = g_statp[layer][tid][0] * inv_m;
        float var = fmaxf(g_statp[layer][HID + tid][0] * inv_m - mu * mu, 0.f);
        float sc = gamma[tid] * rsqrtf(var + EPS);
        s_scale[tid] = sc;
        s_shift[tid] = beta[tid] - mu * sc;
    }
    __syncthreads();

    int idx = blockIdx.x * blockDim.x + tid;   // 4-channel group index
    int total = M * 32;
    if (idx >= total) return;
    int c4 = idx & 31;
    uint2 uz = ((const uint2*)g_zh)[idx];
    float2 z01 = __half22float2(*(__half2*)&uz.x);
    float2 z23 = __half22float2(*(__half2*)&uz.y);
    float4 sc = ((const float4*)s_scale)[c4];
    float4 sh = ((const float4*)s_shift)[c4];
    float4 h;
    h.x = fmaxf(fmaf(z01.x, sc.x, sh.x), 0.f);
    h.y = fmaxf(fmaf(z01.y, sc.y, sh.y), 0.f);
    h.z = fmaxf(fmaf(z23.x, sc.z, sh.z), 0.f);
    h.w = fmaxf(fmaf(z23.y, sc.w, sh.w), 0.f);
    if (write_h) ((float4*)g_h)[idx] = h;

    __nv_bfloat16 hx = __float2bfloat16(h.x);
    __nv_bfloat16 hy = __float2bfloat16(h.y);
    __nv_bfloat16 hz = __float2bfloat16(h.z);
    __nv_bfloat16 hw = __float2bfloat16(h.w);
    __nv_bfloat162* phi = (__nv_bfloat162*)&g_ah_hi[(size_t)idx * 4];
    phi[0] = __nv_bfloat162(hx, hy);
    phi[1] = __nv_bfloat162(hz, hw);
    __nv_bfloat162* plo = (__nv_bfloat162*)&g_ah_lo[(size_t)idx * 4];
    plo[0] = __nv_bfloat162(__float2bfloat16(h.x - __bfloat162float(hx)),
                            __float2bfloat16(h.y - __bfloat162float(hy)));
    plo[1] = __nv_bfloat162(__float2bfloat16(h.z - __bfloat162float(hz)),
                            __float2bfloat16(h.w - __bfloat162float(hw)));
}

// ---------------- global mean pool (segmented, batch sorted) ----------------
__global__ void pool_kernel(int G) {
    int g = blockIdx.x;
    int c = threadIdx.x;
    if (g >= G) return;
    int r0 = g_gstart[g];
    int r1 = g_gstart[g + 1];
    float s = 0.f;
    for (int r = r0; r < r1; r++) s += g_h[(size_t)r * HID + c];
    int cnt = r1 - r0;
    g_pooled[(size_t)g * HID + c] = s / (float)(cnt > 1 ? cnt : 1);
}

// ---------------- MLP head ----------------
__global__ void head_kernel(const float* __restrict__ Wh1,
                            const float* __restrict__ bh1,
                            const float* __restrict__ Wh2,
                            const float* __restrict__ bh2,
                            float* __restrict__ out, int G)
{
    int g = blockIdx.x;
    int t = threadIdx.x;
    if (g >= G) return;
    float acc = bh1[t];
    #pragma unroll 8
    for (int k = 0; k < HID; k++)
        acc = fmaf(g_pooled[(size_t)g * HID + k], Wh1[k * HIDH + t], acc);
    float v = fmaxf(acc, 0.f) * Wh2[t];
    #pragma unroll
    for (int off = 16; off; off >>= 1)
        v += __shfl_down_sync(0xffffffff, v, off);
    __shared__ float sred[2];
    if ((t & 31) == 0) sred[t >> 5] = v;
    __syncthreads();
    if (t == 0) out[g] = sred[0] + sred[1] + bh2[0];
}

// ---------------- launch ----------------
extern "C" void kernel_launch(void* const* d_in, const int* in_sizes, int n_in,
                              void* d_out, int out_size) {
    const float* x     = (const float*)d_in[0];
    const void*  ei    = d_in[1];
    const void*  batch = d_in[2];

    const float* W_n0 = (const float*)d_in[3];
    const float* b0   = (const float*)d_in[4];
    const float* W_r0 = (const float*)d_in[5];
    const float* g0   = (const float*)d_in[6];
    const float* be0  = (const float*)d_in[7];

    const float* W_n1 = (const float*)d_in[8];
    const float* b1   = (const float*)d_in[9];
    const float* W_r1 = (const float*)d_in[10];
    const float* g1   = (const float*)d_in[11];
    const float* be1  = (const float*)d_in[12];

    const float* W_n2 = (const float*)d_in[13];
    const float* b2   = (const float*)d_in[14];
    const float* W_r2 = (const float*)d_in[15];
    const float* g2   = (const float*)d_in[16];
    const float* be2  = (const float*)d_in[17];

    const float* Wh1 = (const float*)d_in[18];
    const float* bh1 = (const float*)d_in[19];
    const float* Wh2 = (const float*)d_in[20];
    const float* bh2 = (const float*)d_in[21];

    float* out = (float*)d_out;

    const int N = in_sizes[2];
    const int E = in_sizes[1] / 2;
    const int G = out_size;
    const int IN_CH = in_sizes[0] / N;

    cudaFuncSetAttribute(gemm_mma_kernel, cudaFuncAttributeMaxDynamicSharedMemorySize,
                         SM_TOTAL);

    // ---- prep: flag/zero, detect dtype, CSR, segments ----
    prep0_kernel<<<(N + 255) / 256, 256>>>(N);
    detect_kernel<<<8, 256>>>(ei, in_sizes[1]);
    int nscan = (N + SCAN_B - 1) / SCAN_B;
    count_edges_kernel<<<(E + 255) / 256, 256>>>(ei, E);
    scan1_kernel<<<nscan, SCAN_B>>>(N);
    scan2_kernel<<<1, 32>>>(nscan);
    scan3_kernel<<<(N + 255) / 256, 256>>>(N, E);
    fill_edges_kernel<<<(E + 255) / 256, 256>>>(ei, E);
    gstart_kernel<<<(N + 256) / 256, 256>>>(batch, N, G);

    // ---- bf16 split preprocessing ----
    convert_x_kernel<<<(N * KPAD + 255) / 256, 256>>>(x, N, IN_CH);
    {
        dim3 wgrid((256 * KPAD + 255) / 256, 3);
        prep_weights_kernel<<<wgrid, 256>>>(W_n0, W_r0, W_n1, W_r1, W_n2, W_r2, IN_CH);
    }

    dim3 gemm_grid((N + 127) / 128, 2);
    int agg_blocks  = (N + 7) / 8;
    int norm_blocks = (N * 32 + 255) / 256;

    const float* bb[3] = {b0, b1, b2};
    const float* gg[3] = {g0, g1, g2};
    const float* be[3] = {be0, be1, be2};

    for (int l = 0; l < 3; l++) {
        const uint4* ahi;
        const uint4* alo;
        const uint4* bhi;
        const uint4* blo;
        void* p;
        cudaGetSymbolAddress(&p, (l == 0) ? g_ax_hi : g_ah_hi); ahi = (const uint4*)p;
        cudaGetSymbolAddress(&p, (l == 0) ? g_ax_lo : g_ah_lo); alo = (const uint4*)p;
        cudaGetSymbolAddress(&p, g_bw_hi); bhi = (const uint4*)p + (size_t)l * (256 * KPAD / 8);
        cudaGetSymbolAddress(&p, g_bw_lo); blo = (const uint4*)p + (size_t)l * (256 * KPAD / 8);

        gemm_mma_kernel<<<gemm_grid, 256, SM_TOTAL>>>(ahi, alo, bhi, blo, bb[l], N);
        aggregate_kernel<<<agg_blocks, 256>>>(N, l);
        norm_relu_kernel<<<norm_blocks, 256>>>(N, l, (l == 2) ? 1 : 0, gg[l], be[l]);
    }

    pool_kernel<<<G, HID>>>(G);
    head_kernel<<<G, HIDH>>>(Wh1, bh1, Wh2, bh2, out, G);
}

// round 13
// speedup vs baseline: 1.1918x; 1.0574x over previous
#include <cuda_runtime.h>
#include <cuda_bf16.h>
#include <cuda_fp16.h>
#include <cstdint>

// ---------------- problem constants ----------------
#define N_NODES_MAX 50000
#define N_EDGES_MAX 800000
#define N_GRAPHS_MAX 1000
#define HID 128
#define HIDH 64
#define KPAD 128
#define EPS 1e-5f
#define SCAN_B 1024
#define MAX_BLOCKS ((N_NODES_MAX + SCAN_B - 1) / SCAN_B)

// ---------------- scratch (device globals, allocation-free) ----------------
__device__ __align__(16) __half g_yh[N_NODES_MAX * HID];    // h @ W_n (fp16)
__device__ __align__(16) __half g_zh[N_NODES_MAX * HID];    // h @ W_r + b + agg (fp16)
__device__ __align__(16) __nv_bfloat16 g_ax_hi[N_NODES_MAX * KPAD];
__device__ __align__(16) __nv_bfloat16 g_ax_lo[N_NODES_MAX * KPAD];
__device__ __align__(16) __nv_bfloat16 g_ah_hi[N_NODES_MAX * KPAD];
__device__ __align__(16) __nv_bfloat16 g_ah_lo[N_NODES_MAX * KPAD];
__device__ __align__(16) __nv_bfloat16 g_bw_hi[3][256 * KPAD];   // [Wn|Wr]^T hi, [n][k]
__device__ __align__(16) __nv_bfloat16 g_bw_lo[3][256 * KPAD];
__device__ int   g_is64;
__device__ int   g_indeg[N_NODES_MAX];
__device__ int   g_rowexcl[N_NODES_MAX];
__device__ int   g_bsum[MAX_BLOCKS];
__device__ int   g_bsumex[MAX_BLOCKS];
__device__ int   g_row_start[N_NODES_MAX + 1];
__device__ int   g_epos[N_NODES_MAX];
__device__ int   g_esrc[N_EDGES_MAX];
__device__ int   g_gstart[N_GRAPHS_MAX + 1];
__device__ float g_statp[3][2 * HID][32];    // padded: one 128B line per stat
// ---------------- index-width handling ----------------
__device__ __forceinline__ int ld_idx(const void* p, long long i, int is64) {
    if (is64) return (int)((const long long*)p)[i];
    return ((const int*)p)[i];
}

// ---------------- combined prep: flag init + zero indeg + zero stats -------
__global__ void prep0_kernel(int N) {
    int i = blockIdx.x * blockDim.x + threadIdx.x;
    if (i == 0) g_is64 = 1;
    if (i < N) g_indeg[i] = 0;
    if (i < 3 * 2 * HID) g_statp[i / (2 * HID)][i % (2 * HID)][0] = 0.f;
}

__global__ void detect_kernel(const void* ei, int n_i32) {
    int i = blockIdx.x * blockDim.x + threadIdx.x;
    int idx = 2 * i + 1;
    if (idx < n_i32 && ((const int*)ei)[idx] != 0) g_is64 = 0;
}

// ---------------- CSR build ----------------
__global__ void count_edges_kernel(const void* __restrict__ ei, int E) {
    int e = blockIdx.x * blockDim.x + threadIdx.x;
    if (e >= E) return;
    atomicAdd(&g_indeg[ld_idx(ei, (long long)E + e, g_is64)], 1);
}

__global__ void scan1_kernel(int N) {
    __shared__ int sh[SCAN_B];
    int i = blockIdx.x * SCAN_B + threadIdx.x;
    int v = (i < N) ? g_indeg[i] : 0;
    sh[threadIdx.x] = v;
    __syncthreads();
    #pragma unroll
    for (int off = 1; off < SCAN_B; off <<= 1) {
        int t = 0;
        if (threadIdx.x >= off) t = sh[threadIdx.x - off];
        __syncthreads();
        sh[threadIdx.x] += t;
        __syncthreads();
    }
    if (i < N) g_rowexcl[i] = sh[threadIdx.x] - v;
    if (threadIdx.x == SCAN_B - 1) g_bsum[blockIdx.x] = sh[SCAN_B - 1];
}

__global__ void scan2_kernel(int nblocks) {
    if (threadIdx.x == 0) {
        int run = 0;
        for (int b = 0; b < nblocks; b++) { int t = g_bsum[b]; g_bsumex[b] = run; run += t; }
    }
}

__global__ void scan3_kernel(int N, int E) {
    int i = blockIdx.x * blockDim.x + threadIdx.x;
    if (i < N) {
        int v = g_rowexcl[i] + g_bsumex[i >> 10];
        g_row_start[i] = v;
        g_epos[i] = v;
    }
    if (i == 0) g_row_start[N] = E;
}

__global__ void fill_edges_kernel(const void* __restrict__ ei, int E) {
    int e = blockIdx.x * blockDim.x + threadIdx.x;
    if (e >= E) return;
    int is64 = g_is64;
    int s = ld_idx(ei, e, is64);
    int d = ld_idx(ei, (long long)E + e, is64);
    g_esrc[atomicAdd(&g_epos[d], 1)] = s;
}

__global__ void gstart_kernel(const void* __restrict__ batch, int N, int G) {
    int i = blockIdx.x * blockDim.x + threadIdx.x;
    if (i > N) return;
    int is64 = g_is64;
    int cur  = (i == N) ? G : ld_idx(batch, i, is64);
    int prev = (i == 0) ? -1 : ld_idx(batch, i - 1, is64);
    for (int g = prev + 1; g <= cur && g <= G; g++) g_gstart[g] = i;
}

// ---------------- bf16 split conversions ----------------
__global__ void convert_x_kernel(const float* __restrict__ x, int N, int IN_CH) {
    int idx = blockIdx.x * blockDim.x + threadIdx.x;
    if (idx >= N * KPAD) return;
    int r = idx >> 7, k = idx & 127;
    float v = (k < IN_CH) ? x[(size_t)r * IN_CH + k] : 0.f;
    __nv_bfloat16 hi = __float2bfloat16(v);
    g_ax_hi[idx] = hi;
    g_ax_lo[idx] = __float2bfloat16(v - __bfloat162float(hi));
}

// one launch for all 3 layers: blockIdx.y = layer
__global__ void prep_weights_kernel(const float* __restrict__ Wn0, const float* __restrict__ Wr0,
                                    const float* __restrict__ Wn1, const float* __restrict__ Wr1,
                                    const float* __restrict__ Wn2, const float* __restrict__ Wr2,
                                    int IN_CH) {
    int idx = blockIdx.x * blockDim.x + threadIdx.x;
    if (idx >= 256 * KPAD) return;
    int layer = blockIdx.y;
    const float* Wn = (layer == 0) ? Wn0 : (layer == 1) ? Wn1 : Wn2;
    const float* Wr = (layer == 0) ? Wr0 : (layer == 1) ? Wr1 : Wr2;
    int K_real = (layer == 0) ? IN_CH : HID;
    int n = idx >> 7, k = idx & 127;
    float v = 0.f;
    if (k < K_real) v = (n < HID) ? Wn[(size_t)k * HID + n] : Wr[(size_t)k * HID + (n - HID)];
    __nv_bfloat16 hi = __float2bfloat16(v);
    g_bw_hi[layer][idx] = hi;
    g_bw_lo[layer][idx] = __float2bfloat16(v - __bfloat162float(hi));
}

// ---------------- mma.sync dual GEMM (split halves, 3-tile SMEM) -----------
// Template on KSTEPS (k16 steps used): 5 for layer 0 (K=80), 8 for layers 1/2.
// Buffer layouts are IDENTICAL for both (stride 16 uint4); only loop bounds shrink.
// grid (nb, 2). blockIdx.y: 0 -> g_yh (fp16), 1 -> g_zh (fp16 + bias).
// Phase 1: A_hi x (B_hi, B_lo) with shared A fragments; [reload A with A_lo];
// Phase 2: A_lo x B_hi.
#define PITCH 272
#define A_TILE (128 * PITCH)            // 34816
#define SM_A    0
#define SM_B_HI A_TILE
#define SM_B_LO (2 * A_TILE)
#define SM_TOTAL (3 * A_TILE)           // 104448

__device__ __forceinline__ uint32_t smem_u32(const void* p) {
    uint32_t a;
    asm("{ .reg .u64 t; cvta.to.shared.u64 t, %1; cvt.u32.u64 %0, t; }" : "=r"(a) : "l"(p));
    return a;
}

__device__ __forceinline__ void ldsm_x4(uint32_t& r0, uint32_t& r1, uint32_t& r2, uint32_t& r3,
                                        uint32_t addr) {
    asm volatile("ldmatrix.sync.aligned.m8n8.x4.shared.b16 {%0,%1,%2,%3}, [%4];"
                 : "=r"(r0), "=r"(r1), "=r"(r2), "=r"(r3) : "r"(addr));
}

__device__ __forceinline__ void mma16816(float* c, const uint32_t* a, const uint32_t* b) {
    asm volatile(
        "mma.sync.aligned.m16n8k16.row.col.f32.bf16.bf16.f32 "
        "{%0,%1,%2,%3}, {%4,%5,%6,%7}, {%8,%9}, {%0,%1,%2,%3};"
        : "+f"(c[0]), "+f"(c[1]), "+f"(c[2]), "+f"(c[3])
        : "r"(a[0]), "r"(a[1]), "r"(a[2]), "r"(a[3]), "r"(b[0]), "r"(b[1]));
}

template <int KSTEPS>
__global__ __launch_bounds__(256, 2)
void gemm_mma_kernel(const uint4* __restrict__ a_hi, const uint4* __restrict__ a_lo,
                     const uint4* __restrict__ b_hi, const uint4* __restrict__ b_lo,
                     const float* __restrict__ bias, int M)
{
    constexpr int CR = 2 * KSTEPS;      // uint4 column-chunks actually used per row
    extern __shared__ char smem[];
    uint32_t sbase = smem_u32(smem);

    int tid = threadIdx.x;
    int lane = tid & 31;
    int wid = tid >> 5;
    int wm = wid & 3;
    int wn = wid >> 2;
    int row0 = blockIdx.x * 128;
    int half = blockIdx.y;
    int brow0 = half * 128;

    // ---- load A_hi + both B tiles (only CR of 16 chunks per row) ----
    #pragma unroll
    for (int i = tid; i < 128 * CR; i += 256) {
        int r = i / CR, c16 = i % CR;
        int doff = r * PITCH + c16 * 16;
        uint4 vh = make_uint4(0, 0, 0, 0);
        if (row0 + r < M) vh = a_hi[(size_t)(row0 + r) * 16 + c16];
        *(uint4*)(smem + SM_A + doff) = vh;
        *(uint4*)(smem + SM_B_HI + doff) = b_hi[(size_t)(brow0 + r) * 16 + c16];
        *(uint4*)(smem + SM_B_LO + doff) = b_lo[(size_t)(brow0 + r) * 16 + c16];
    }
    __syncthreads();

    float acc[2][8][4];
    #pragma unroll
    for (int mi = 0; mi < 2; mi++)
        #pragma unroll
        for (int ni = 0; ni < 8; ni++)
            #pragma unroll
            for (int q = 0; q < 4; q++) acc[mi][ni][q] = 0.f;

    uint32_t a_off[2];
    #pragma unroll
    for (int mi = 0; mi < 2; mi++)
        a_off[mi] = (uint32_t)((wm * 32 + mi * 16 + (lane & 15)) * PITCH + (lane >> 4) * 16);
    uint32_t b_off[4];
    {
        int grp = lane >> 3, rin = lane & 7;
        int radd = (grp >= 2) ? 8 : 0;
        int koff = (grp & 1) * 16;
        #pragma unroll
        for (int pi = 0; pi < 4; pi++)
            b_off[pi] = (uint32_t)((wn * 64 + pi * 16 + radd + rin) * PITCH + koff);
    }

    uint32_t smA  = sbase + SM_A;
    uint32_t smBH = sbase + SM_B_HI;
    uint32_t smBL = sbase + SM_B_LO;

    // ---- phase 1: A_hi x B_hi and A_hi x B_lo (shared A fragments) ----
    #pragma unroll
    for (int k16 = 0; k16 < KSTEPS; k16++) {
        uint32_t kadd = k16 * 32;
        uint32_t afr[2][4];
        #pragma unroll
        for (int mi = 0; mi < 2; mi++)
            ldsm_x4(afr[mi][0], afr[mi][1], afr[mi][2], afr[mi][3],
                    smA + a_off[mi] + kadd);
        uint32_t bfr[8][2];
        #pragma unroll
        for (int pi = 0; pi < 4; pi++) {
            uint32_t r0, r1, r2, r3;
            ldsm_x4(r0, r1, r2, r3, smBH + b_off[pi] + kadd);
            bfr[pi * 2][0] = r0; bfr[pi * 2][1] = r1;
            bfr[pi * 2 + 1][0] = r2; bfr[pi * 2 + 1][1] = r3;
        }
        #pragma unroll
        for (int ni = 0; ni < 8; ni++) {
            mma16816(acc[0][ni], afr[0], bfr[ni]);
            mma16816(acc[1][ni], afr[1], bfr[ni]);
        }
        #pragma unroll
        for (int pi = 0; pi < 4; pi++) {
            uint32_t r0, r1, r2, r3;
            ldsm_x4(r0, r1, r2, r3, smBL + b_off[pi] + kadd);
            bfr[pi * 2][0] = r0; bfr[pi * 2][1] = r1;
            bfr[pi * 2 + 1][0] = r2; bfr[pi * 2 + 1][1] = r3;
        }
        #pragma unroll
        for (int ni = 0; ni < 8; ni++) {
            mma16816(acc[0][ni], afr[0], bfr[ni]);
            mma16816(acc[1][ni], afr[1], bfr[ni]);
        }
    }

    // ---- reload A tile with A_lo ----
    __syncthreads();
    #pragma unroll
    for (int i = tid; i < 128 * CR; i += 256) {
        int r = i / CR, c16 = i % CR;
        int doff = r * PITCH + c16 * 16;
        uint4 vl = make_uint4(0, 0, 0, 0);
        if (row0 + r < M) vl = a_lo[(size_t)(row0 + r) * 16 + c16];
        *(uint4*)(smem + SM_A + doff) = vl;
    }
    __syncthreads();

    // ---- phase 2: A_lo x B_hi ----
    #pragma unroll
    for (int k16 = 0; k16 < KSTEPS; k16++) {
        uint32_t kadd = k16 * 32;
        uint32_t afr[2][4];
        #pragma unroll
        for (int mi = 0; mi < 2; mi++)
            ldsm_x4(afr[mi][0], afr[mi][1], afr[mi][2], afr[mi][3],
                    smA + a_off[mi] + kadd);
        uint32_t bfr[8][2];
        #pragma unroll
        for (int pi = 0; pi < 4; pi++) {
            uint32_t r0, r1, r2, r3;
            ldsm_x4(r0, r1, r2, r3, smBH + b_off[pi] + kadd);
            bfr[pi * 2][0] = r0; bfr[pi * 2][1] = r1;
            bfr[pi * 2 + 1][0] = r2; bfr[pi * 2 + 1][1] = r3;
        }
        #pragma unroll
        for (int ni = 0; ni < 8; ni++) {
            mma16816(acc[0][ni], afr[0], bfr[ni]);
            mma16816(acc[1][ni], afr[1], bfr[ni]);
        }
    }

    // ---- epilogue: half 0 -> g_yh (fp16), half 1 -> g_zh (fp16 + bias) ----
    __half* O = half ? g_zh : g_yh;
    #pragma unroll
    for (int mi = 0; mi < 2; mi++) {
        int r0 = row0 + wm * 32 + mi * 16 + (lane >> 2);
        #pragma unroll
        for (int ni = 0; ni < 8; ni++) {
            int c = wn * 64 + ni * 8 + (lane & 3) * 2;
            float bx = 0.f, by = 0.f;
            if (half) { bx = bias[c]; by = bias[c + 1]; }
            if (r0 < M) {
                __half2 v = __floats2half2_rn(acc[mi][ni][0] + bx, acc[mi][ni][1] + by);
                *(__half2*)&O[(size_t)r0 * HID + c] = v;
            }
            if (r0 + 8 < M) {
                __half2 v = __floats2half2_rn(acc[mi][ni][2] + bx, acc[mi][ni][3] + by);
                *(__half2*)&O[(size_t)(r0 + 8) * HID + c] = v;
            }
        }
    }
}

// ---------------- gather-mean + fused BN stats ------------------------------
__global__ void aggregate_kernel(int N, int layer) {
    __shared__ float sh_s[8][132];
    __shared__ float sh_q[8][132];
    int wid = threadIdx.x >> 5;
    int lane = threadIdx.x & 31;
    int d = blockIdx.x * 8 + wid;

    float4 z = make_float4(0.f, 0.f, 0.f, 0.f);
    if (d < N) {
        int s0 = g_row_start[d];
        int s1 = g_row_start[d + 1];
        int deg = s1 - s0;
        float inv = 1.0f / (float)(deg > 1 ? deg : 1);
        const uint2* Y = (const uint2*)g_yh;

        float4 acc = make_float4(0.f, 0.f, 0.f, 0.f);
        int j = s0;
        for (; j + 3 < s1; j += 4) {
            uint2 ua = Y[(size_t)g_esrc[j] * 32 + lane];
            uint2 ub = Y[(size_t)g_esrc[j + 1] * 32 + lane];
            uint2 uc = Y[(size_t)g_esrc[j + 2] * 32 + lane];
            uint2 ud = Y[(size_t)g_esrc[j + 3] * 32 + lane];
            float2 a0 = __half22float2(*(__half2*)&ua.x), a1 = __half22float2(*(__half2*)&ua.y);
            float2 b0 = __half22float2(*(__half2*)&ub.x), b1 = __half22float2(*(__half2*)&ub.y);
            float2 c0 = __half22float2(*(__half2*)&uc.x), c1 = __half22float2(*(__half2*)&uc.y);
            float2 d0 = __half22float2(*(__half2*)&ud.x), d1 = __half22float2(*(__half2*)&ud.y);
            acc.x += (a0.x + b0.x) + (c0.x + d0.x);
            acc.y += (a0.y + b0.y) + (c0.y + d0.y);
            acc.z += (a1.x + b1.x) + (c1.x + d1.x);
            acc.w += (a1.y + b1.y) + (c1.y + d1.y);
        }
        for (; j < s1; j++) {
            uint2 ua = Y[(size_t)g_esrc[j] * 32 + lane];
            float2 a0 = __half22float2(*(__half2*)&ua.x), a1 = __half22float2(*(__half2*)&ua.y);
            acc.x += a0.x; acc.y += a0.y; acc.z += a1.x; acc.w += a1.y;
        }

        uint2 uz = ((const uint2*)g_zh)[(size_t)d * 32 + lane];
        float2 z01 = __half22float2(*(__half2*)&uz.x);
        float2 z23 = __half22float2(*(__half2*)&uz.y);
        z.x = fmaf(acc.x, inv, z01.x);
        z.y = fmaf(acc.y, inv, z01.y);
        z.z = fmaf(acc.z, inv, z23.x);
        z.w = fmaf(acc.w, inv, z23.y);
        uint2 uo;
        *(__half2*)&uo.x = __floats2half2_rn(z.x, z.y);
        *(__half2*)&uo.y = __floats2half2_rn(z.z, z.w);
        ((uint2*)g_zh)[(size_t)d * 32 + lane] = uo;
    }

    // fused BN stats
    float4 q = make_float4(z.x * z.x, z.y * z.y, z.z * z.z, z.w * z.w);
    *(float4*)&sh_s[wid][4 * lane] = z;
    *(float4*)&sh_q[wid][4 * lane] = q;
    __syncthreads();
    int t = threadIdx.x;
    if (t < HID) {
        float s = 0.f;
        #pragma unroll
        for (int w = 0; w < 8; w++) s += sh_s[w][t];
        atomicAdd(&g_statp[layer][t][0], s);
    } else {
        int c = t - HID;
        float s = 0.f;
        #pragma unroll
        for (int w = 0; w < 8; w++) s += sh_q[w][c];
        atomicAdd(&g_statp[layer][HID + c][0], s);
    }
}

// fused: compute scale/shift per block, h = relu(z*sc+sh), emit bf16 hi/lo
__global__ void norm_relu_kernel(int M, int layer,
                                 const float* __restrict__ gamma,
                                 const float* __restrict__ beta) {
    __shared__ float s_scale[HID];
    __shared__ float s_shift[HID];
    int tid = threadIdx.x;
    if (tid < HID) {
        float inv_m = 1.0f / (float)M;
        float mu = g_statp[layer][tid][0] * inv_m;
        float var = fmaxf(g_statp[layer][HID + tid][0] * inv_m - mu * mu, 0.f);
        float sc = gamma[tid] * rsqrtf(var + EPS);
        s_scale[tid] = sc;
        s_shift[tid] = beta[tid] - mu * sc;
    }
    __syncthreads();

    int idx = blockIdx.x * blockDim.x + tid;   // 4-channel group index
    int total = M * 32;
    if (idx >= total) return;
    int c4 = idx & 31;
    uint2 uz = ((const uint2*)g_zh)[idx];
    float2 z01 = __half22float2(*(__half2*)&uz.x);
    float2 z23 = __half22float2(*(__half2*)&uz.y);
    float4 sc = ((const float4*)s_scale)[c4];
    float4 sh = ((const float4*)s_shift)[c4];
    float4 h;
    h.x = fmaxf(fmaf(z01.x, sc.x, sh.x), 0.f);
    h.y = fmaxf(fmaf(z01.y, sc.y, sh.y), 0.f);
    h.z = fmaxf(fmaf(z23.x, sc.z, sh.z), 0.f);
    h.w = fmaxf(fmaf(z23.y, sc.w, sh.w), 0.f);

    __nv_bfloat16 hx = __float2bfloat16(h.x);
    __nv_bfloat16 hy = __float2bfloat16(h.y);
    __nv_bfloat16 hz = __float2bfloat16(h.z);
    __nv_bfloat16 hw = __float2bfloat16(h.w);
    __nv_bfloat162* phi = (__nv_bfloat162*)&g_ah_hi[(size_t)idx * 4];
    phi[0] = __nv_bfloat162(hx, hy);
    phi[1] = __nv_bfloat162(hz, hw);
    __nv_bfloat162* plo = (__nv_bfloat162*)&g_ah_lo[(size_t)idx * 4];
    plo[0] = __nv_bfloat162(__float2bfloat16(h.x - __bfloat162float(hx)),
                            __float2bfloat16(h.y - __bfloat162float(hy)));
    plo[1] = __nv_bfloat162(__float2bfloat16(h.z - __bfloat162float(hz)),
                            __float2bfloat16(h.w - __bfloat162float(hw)));
}

// ---------------- fused global mean pool + MLP head -------------------------
// h is reconstructed exactly (to 2^-16) as hi + lo from the bf16 split arrays.
__global__ void pool_head_kernel(const float* __restrict__ Wh1,
                                 const float* __restrict__ bh1,
                                 const float* __restrict__ Wh2,
                                 const float* __restrict__ bh2,
                                 float* __restrict__ out, int G)
{
    __shared__ float pooled[HID];
    __shared__ float sred[2];
    int g = blockIdx.x;
    int t = threadIdx.x;   // 0..127
    if (g >= G) return;
    int r0 = g_gstart[g];
    int r1 = g_gstart[g + 1];
    float s = 0.f;
    for (int r = r0; r < r1; r++) {
        float hi = __bfloat162float(g_ah_hi[(size_t)r * HID + t]);
        float lo = __bfloat162float(g_ah_lo[(size_t)r * HID + t]);
        s += hi + lo;
    }
    int cnt = r1 - r0;
    pooled[t] = s / (float)(cnt > 1 ? cnt : 1);
    __syncthreads();

    if (t < HIDH) {
        float acc = bh1[t];
        #pragma unroll 8
        for (int k = 0; k < HID; k++)
            acc = fmaf(pooled[k], Wh1[k * HIDH + t], acc);
        float v = fmaxf(acc, 0.f) * Wh2[t];
        #pragma unroll
        for (int off = 16; off; off >>= 1)
            v += __shfl_down_sync(0xffffffff, v, off);
        if ((t & 31) == 0) sred[t >> 5] = v;
    }
    __syncthreads();
    if (t == 0) out[g] = sred[0] + sred[1] + bh2[0];
}

// ---------------- launch ----------------
extern "C" void kernel_launch(void* const* d_in, const int* in_sizes, int n_in,
                              void* d_out, int out_size) {
    const float* x     = (const float*)d_in[0];
    const void*  ei    = d_in[1];
    const void*  batch = d_in[2];

    const float* W_n0 = (const float*)d_in[3];
    const float* b0   = (const float*)d_in[4];
    const float* W_r0 = (const float*)d_in[5];
    const float* g0   = (const float*)d_in[6];
    const float* be0  = (const float*)d_in[7];

    const float* W_n1 = (const float*)d_in[8];
    const float* b1   = (const float*)d_in[9];
    const float* W_r1 = (const float*)d_in[10];
    const float* g1   = (const float*)d_in[11];
    const float* be1  = (const float*)d_in[12];

    const float* W_n2 = (const float*)d_in[13];
    const float* b2   = (const float*)d_in[14];
    const float* W_r2 = (const float*)d_in[15];
    const float* g2   = (const float*)d_in[16];
    const float* be2  = (const float*)d_in[17];

    const float* Wh1 = (const float*)d_in[18];
    const float* bh1 = (const float*)d_in[19];
    const float* Wh2 = (const float*)d_in[20];
    const float* bh2 = (const float*)d_in[21];

    float* out = (float*)d_out;

    const int N = in_sizes[2];
    const int E = in_sizes[1] / 2;
    const int G = out_size;
    const int IN_CH = in_sizes[0] / N;

    cudaFuncSetAttribute(gemm_mma_kernel<5>, cudaFuncAttributeMaxDynamicSharedMemorySize,
                         SM_TOTAL);
    cudaFuncSetAttribute(gemm_mma_kernel<8>, cudaFuncAttributeMaxDynamicSharedMemorySize,
                         SM_TOTAL);

    // ---- prep: flag/zero, detect dtype, CSR, segments ----
    prep0_kernel<<<(N + 255) / 256, 256>>>(N);
    detect_kernel<<<8, 256>>>(ei, in_sizes[1]);
    int nscan = (N + SCAN_B - 1) / SCAN_B;
    count_edges_kernel<<<(E + 255) / 256, 256>>>(ei, E);
    scan1_kernel<<<nscan, SCAN_B>>>(N);
    scan2_kernel<<<1, 32>>>(nscan);
    scan3_kernel<<<(N + 255) / 256, 256>>>(N, E);
    fill_edges_kernel<<<(E + 255) / 256, 256>>>(ei, E);
    gstart_kernel<<<(N + 256) / 256, 256>>>(batch, N, G);

    // ---- bf16 split preprocessing ----
    convert_x_kernel<<<(N * KPAD + 255) / 256, 256>>>(x, N, IN_CH);
    {
        dim3 wgrid((256 * KPAD + 255) / 256, 3);
        prep_weights_kernel<<<wgrid, 256>>>(W_n0, W_r0, W_n1, W_r1, W_n2, W_r2, IN_CH);
    }

    dim3 gemm_grid((N + 127) / 128, 2);
    int agg_blocks  = (N + 7) / 8;
    int norm_blocks = (N * 32 + 255) / 256;
    int ksteps0 = (IN_CH + 15) / 16;   // 5 for IN_CH=78

    const float* bb[3] = {b0, b1, b2};
    const float* gg[3] = {g0, g1, g2};
    const float* be[3] = {be0, be1, be2};

    for (int l = 0; l < 3; l++) {
        const uint4* ahi;
        const uint4* alo;
        const uint4* bhi;
        const uint4* blo;
        void* p;
        cudaGetSymbolAddress(&p, (l == 0) ? g_ax_hi : g_ah_hi); ahi = (const uint4*)p;
        cudaGetSymbolAddress(&p, (l == 0) ? g_ax_lo : g_ah_lo); alo = (const uint4*)p;
        cudaGetSymbolAddress(&p, g_bw_hi); bhi = (const uint4*)p + (size_t)l * (256 * KPAD / 8);
        cudaGetSymbolAddress(&p, g_bw_lo); blo = (const uint4*)p + (size_t)l * (256 * KPAD / 8);

        if (l == 0 && ksteps0 <= 5)
            gemm_mma_kernel<5><<<gemm_grid, 256, SM_TOTAL>>>(ahi, alo, bhi, blo, bb[l], N);
        else
            gemm_mma_kernel<8><<<gemm_grid, 256, SM_TOTAL>>>(ahi, alo, bhi, blo, bb[l], N);
        aggregate_kernel<<<agg_blocks, 256>>>(N, l);
        norm_relu_kernel<<<norm_blocks, 256>>>(N, l, gg[l], be[l]);
    }

    pool_head_kernel<<<G, HID>>>(Wh1, bh1, Wh2, bh2, out, G);
}

// round 14
// speedup vs baseline: 1.2480x; 1.0471x over previous
#include <cuda_runtime.h>
#include <cuda_bf16.h>
#include <cuda_fp16.h>
#include <cstdint>

// ---------------- problem constants ----------------
#define N_NODES_MAX 50000
#define N_EDGES_MAX 800000
#define N_GRAPHS_MAX 1000
#define HID 128
#define HIDH 64
#define KPAD 128
#define EPS 1e-5f
#define SCAN_B 1024
#define MAX_BLOCKS ((N_NODES_MAX + SCAN_B - 1) / SCAN_B)

// ---------------- scratch (device globals, allocation-free) ----------------
__device__ __align__(16) __half g_yh[N_NODES_MAX * HID];    // h @ W_n (fp16)
__device__ __align__(16) __half g_zh[N_NODES_MAX * HID];    // h @ W_r + b + agg (fp16)
__device__ __align__(16) __nv_bfloat16 g_ax_hi[N_NODES_MAX * KPAD];  // layer-0 A split
__device__ __align__(16) __nv_bfloat16 g_ax_lo[N_NODES_MAX * KPAD];
__device__ __align__(16) __nv_bfloat16 g_bw_hi[3][256 * KPAD];   // [Wn|Wr]^T hi, [n][k]
__device__ __align__(16) __nv_bfloat16 g_bw_lo[3][256 * KPAD];
__device__ int   g_is64;
__device__ int   g_indeg[N_NODES_MAX];
__device__ int   g_rowexcl[N_NODES_MAX];
__device__ int   g_bsum[MAX_BLOCKS];
__device__ int   g_bsumex[MAX_BLOCKS];
__device__ int   g_row_start[N_NODES_MAX + 1];
__device__ int   g_epos[N_NODES_MAX];
__device__ int   g_esrc[N_EDGES_MAX];
__device__ int   g_gstart[N_GRAPHS_MAX + 1];
__device__ float g_statp[3][2 * HID][32];    // padded: one 128B line per stat

// ---------------- index-width handling ----------------
__device__ __forceinline__ int ld_idx(const void* p, long long i, int is64) {
    if (is64) return (int)((const long long*)p)[i];
    return ((const int*)p)[i];
}

// ---------------- combined prep: flag init + zero indeg + zero stats -------
__global__ void prep0_kernel(int N) {
    int i = blockIdx.x * blockDim.x + threadIdx.x;
    if (i == 0) g_is64 = 1;
    if (i < N) g_indeg[i] = 0;
    if (i < 3 * 2 * HID) g_statp[i / (2 * HID)][i % (2 * HID)][0] = 0.f;
}

__global__ void detect_kernel(const void* ei, int n_i32) {
    int i = blockIdx.x * blockDim.x + threadIdx.x;
    int idx = 2 * i + 1;
    if (idx < n_i32 && ((const int*)ei)[idx] != 0) g_is64 = 0;
}

// ---------------- CSR build ----------------
__global__ void count_edges_kernel(const void* __restrict__ ei, int E) {
    int e = blockIdx.x * blockDim.x + threadIdx.x;
    if (e >= E) return;
    atomicAdd(&g_indeg[ld_idx(ei, (long long)E + e, g_is64)], 1);
}

__global__ void scan1_kernel(int N) {
    __shared__ int sh[SCAN_B];
    int i = blockIdx.x * SCAN_B + threadIdx.x;
    int v = (i < N) ? g_indeg[i] : 0;
    sh[threadIdx.x] = v;
    __syncthreads();
    #pragma unroll
    for (int off = 1; off < SCAN_B; off <<= 1) {
        int t = 0;
        if (threadIdx.x >= off) t = sh[threadIdx.x - off];
        __syncthreads();
        sh[threadIdx.x] += t;
        __syncthreads();
    }
    if (i < N) g_rowexcl[i] = sh[threadIdx.x] - v;
    if (threadIdx.x == SCAN_B - 1) g_bsum[blockIdx.x] = sh[SCAN_B - 1];
}

__global__ void scan2_kernel(int nblocks) {
    if (threadIdx.x == 0) {
        int run = 0;
        for (int b = 0; b < nblocks; b++) { int t = g_bsum[b]; g_bsumex[b] = run; run += t; }
    }
}

__global__ void scan3_kernel(int N, int E) {
    int i = blockIdx.x * blockDim.x + threadIdx.x;
    if (i < N) {
        int v = g_rowexcl[i] + g_bsumex[i >> 10];
        g_row_start[i] = v;
        g_epos[i] = v;
    }
    if (i == 0) g_row_start[N] = E;
}

__global__ void fill_edges_kernel(const void* __restrict__ ei, int E) {
    int e = blockIdx.x * blockDim.x + threadIdx.x;
    if (e >= E) return;
    int is64 = g_is64;
    int s = ld_idx(ei, e, is64);
    int d = ld_idx(ei, (long long)E + e, is64);
    g_esrc[atomicAdd(&g_epos[d], 1)] = s;
}

__global__ void gstart_kernel(const void* __restrict__ batch, int N, int G) {
    int i = blockIdx.x * blockDim.x + threadIdx.x;
    if (i > N) return;
    int is64 = g_is64;
    int cur  = (i == N) ? G : ld_idx(batch, i, is64);
    int prev = (i == 0) ? -1 : ld_idx(batch, i - 1, is64);
    for (int g = prev + 1; g <= cur && g <= G; g++) g_gstart[g] = i;
}

// ---------------- bf16 split conversions ----------------
__global__ void convert_x_kernel(const float* __restrict__ x, int N, int IN_CH) {
    int idx = blockIdx.x * blockDim.x + threadIdx.x;
    if (idx >= N * KPAD) return;
    int r = idx >> 7, k = idx & 127;
    float v = (k < IN_CH) ? x[(size_t)r * IN_CH + k] : 0.f;
    __nv_bfloat16 hi = __float2bfloat16(v);
    g_ax_hi[idx] = hi;
    g_ax_lo[idx] = __float2bfloat16(v - __bfloat162float(hi));
}

// one launch for all 3 layers: blockIdx.y = layer
__global__ void prep_weights_kernel(const float* __restrict__ Wn0, const float* __restrict__ Wr0,
                                    const float* __restrict__ Wn1, const float* __restrict__ Wr1,
                                    const float* __restrict__ Wn2, const float* __restrict__ Wr2,
                                    int IN_CH) {
    int idx = blockIdx.x * blockDim.x + threadIdx.x;
    if (idx >= 256 * KPAD) return;
    int layer = blockIdx.y;
    const float* Wn = (layer == 0) ? Wn0 : (layer == 1) ? Wn1 : Wn2;
    const float* Wr = (layer == 0) ? Wr0 : (layer == 1) ? Wr1 : Wr2;
    int K_real = (layer == 0) ? IN_CH : HID;
    int n = idx >> 7, k = idx & 127;
    float v = 0.f;
    if (k < K_real) v = (n < HID) ? Wn[(size_t)k * HID + n] : Wr[(size_t)k * HID + (n - HID)];
    __nv_bfloat16 hi = __float2bfloat16(v);
    g_bw_hi[layer][idx] = hi;
    g_bw_lo[layer][idx] = __float2bfloat16(v - __bfloat162float(hi));
}

// ---------------- mma.sync dual GEMM (split halves, 3-tile SMEM) -----------
// Template: KSTEPS = k16 steps (5 for layer 0, 8 for layers 1/2);
//           NORM   = A comes from g_zh with fused BN+ReLU+bf16-split
// grid (nb, 2). blockIdx.y: 0 -> g_yh (fp16), 1 -> g_zh (fp16 + bias).
// Phase 1: A_hi x (B_hi, B_lo); [reload A with A_lo]; Phase 2: A_lo x B_hi.
#define PITCH 272
#define A_TILE (128 * PITCH)            // 34816
#define SM_A    0
#define SM_B_HI A_TILE
#define SM_B_LO (2 * A_TILE)
#define SM_TOTAL (3 * A_TILE)           // 104448

__device__ __forceinline__ uint32_t smem_u32(const void* p) {
    uint32_t a;
    asm("{ .reg .u64 t; cvta.to.shared.u64 t, %1; cvt.u32.u64 %0, t; }" : "=r"(a) : "l"(p));
    return a;
}

__device__ __forceinline__ void ldsm_x4(uint32_t& r0, uint32_t& r1, uint32_t& r2, uint32_t& r3,
                                        uint32_t addr) {
    asm volatile("ldmatrix.sync.aligned.m8n8.x4.shared.b16 {%0,%1,%2,%3}, [%4];"
                 : "=r"(r0), "=r"(r1), "=r"(r2), "=r"(r3) : "r"(addr));
}

__device__ __forceinline__ void mma16816(float* c, const uint32_t* a, const uint32_t* b) {
    asm volatile(
        "mma.sync.aligned.m16n8k16.row.col.f32.bf16.bf16.f32 "
        "{%0,%1,%2,%3}, {%4,%5,%6,%7}, {%8,%9}, {%0,%1,%2,%3};"
        : "+f"(c[0]), "+f"(c[1]), "+f"(c[2]), "+f"(c[3])
        : "r"(a[0]), "r"(a[1]), "r"(a[2]), "r"(a[3]), "r"(b[0]), "r"(b[1]));
}

// convert one 8-element chunk of z-row into normed/relu'd fp32
__device__ __forceinline__ void z_to_h8(const __half* zrow, const float* s_sc,
                                        const float* s_sh, int cbase, float* h) {
    uint4 vz = *(const uint4*)zrow;
    const __half2* hp = (const __half2*)&vz;
    #pragma unroll
    for (int j = 0; j < 4; j++) {
        float2 f = __half22float2(hp[j]);
        h[2 * j]     = f.x;
        h[2 * j + 1] = f.y;
    }
    #pragma unroll
    for (int j = 0; j < 8; j++)
        h[j] = fmaxf(fmaf(h[j], s_sc[cbase + j], s_sh[cbase + j]), 0.f);
}

template <int KSTEPS, bool NORM>
__global__ __launch_bounds__(256, 2)
void gemm_mma_kernel(const uint4* __restrict__ a_hi, const uint4* __restrict__ a_lo,
                     const uint4* __restrict__ b_hi, const uint4* __restrict__ b_lo,
                     const float* __restrict__ bias,
                     const float* __restrict__ pgamma, const float* __restrict__ pbeta,
                     int prev_layer, int M)
{
    constexpr int CR = 2 * KSTEPS;      // uint4 column-chunks used per row
    extern __shared__ char smem[];
    __shared__ float s_sc[HID];
    __shared__ float s_sh[HID];
    uint32_t sbase = smem_u32(smem);

    int tid = threadIdx.x;
    int lane = tid & 31;
    int wid = tid >> 5;
    int wm = wid & 3;
    int wn = wid >> 2;
    int row0 = blockIdx.x * 128;
    int half = blockIdx.y;
    int brow0 = half * 128;

    if (NORM) {
        if (tid < HID) {
            float inv_m = 1.0f / (float)M;
            float mu = g_statp[prev_layer][tid][0] * inv_m;
            float var = fmaxf(g_statp[prev_layer][HID + tid][0] * inv_m - mu * mu, 0.f);
            float sc = pgamma[tid] * rsqrtf(var + EPS);
            s_sc[tid] = sc;
            s_sh[tid] = pbeta[tid] - mu * sc;
        }
        __syncthreads();
    }

    // ---- load A_hi + both B tiles ----
    #pragma unroll
    for (int i = tid; i < 128 * CR; i += 256) {
        int r = i / CR, c16 = i % CR;
        int doff = r * PITCH + c16 * 16;
        uint4 vh = make_uint4(0, 0, 0, 0);
        if (row0 + r < M) {
            if (NORM) {
                float h[8];
                z_to_h8(g_zh + (size_t)(row0 + r) * HID + c16 * 8, s_sc, s_sh, c16 * 8, h);
                __nv_bfloat162* o = (__nv_bfloat162*)&vh;
                #pragma unroll
                for (int j = 0; j < 4; j++)
                    o[j] = __nv_bfloat162(__float2bfloat16(h[2 * j]),
                                          __float2bfloat16(h[2 * j + 1]));
            } else {
                vh = a_hi[(size_t)(row0 + r) * 16 + c16];
            }
        }
        *(uint4*)(smem + SM_A + doff) = vh;
        *(uint4*)(smem + SM_B_HI + doff) = b_hi[(size_t)(brow0 + r) * 16 + c16];
        *(uint4*)(smem + SM_B_LO + doff) = b_lo[(size_t)(brow0 + r) * 16 + c16];
    }
    __syncthreads();

    float acc[2][8][4];
    #pragma unroll
    for (int mi = 0; mi < 2; mi++)
        #pragma unroll
        for (int ni = 0; ni < 8; ni++)
            #pragma unroll
            for (int q = 0; q < 4; q++) acc[mi][ni][q] = 0.f;

    uint32_t a_off[2];
    #pragma unroll
    for (int mi = 0; mi < 2; mi++)
        a_off[mi] = (uint32_t)((wm * 32 + mi * 16 + (lane & 15)) * PITCH + (lane >> 4) * 16);
    uint32_t b_off[4];
    {
        int grp = lane >> 3, rin = lane & 7;
        int radd = (grp >= 2) ? 8 : 0;
        int koff = (grp & 1) * 16;
        #pragma unroll
        for (int pi = 0; pi < 4; pi++)
            b_off[pi] = (uint32_t)((wn * 64 + pi * 16 + radd + rin) * PITCH + koff);
    }

    uint32_t smA  = sbase + SM_A;
    uint32_t smBH = sbase + SM_B_HI;
    uint32_t smBL = sbase + SM_B_LO;

    // ---- phase 1: A_hi x B_hi and A_hi x B_lo (shared A fragments) ----
    #pragma unroll
    for (int k16 = 0; k16 < KSTEPS; k16++) {
        uint32_t kadd = k16 * 32;
        uint32_t afr[2][4];
        #pragma unroll
        for (int mi = 0; mi < 2; mi++)
            ldsm_x4(afr[mi][0], afr[mi][1], afr[mi][2], afr[mi][3],
                    smA + a_off[mi] + kadd);
        uint32_t bfr[8][2];
        #pragma unroll
        for (int pi = 0; pi < 4; pi++) {
            uint32_t r0, r1, r2, r3;
            ldsm_x4(r0, r1, r2, r3, smBH + b_off[pi] + kadd);
            bfr[pi * 2][0] = r0; bfr[pi * 2][1] = r1;
            bfr[pi * 2 + 1][0] = r2; bfr[pi * 2 + 1][1] = r3;
        }
        #pragma unroll
        for (int ni = 0; ni < 8; ni++) {
            mma16816(acc[0][ni], afr[0], bfr[ni]);
            mma16816(acc[1][ni], afr[1], bfr[ni]);
        }
        #pragma unroll
        for (int pi = 0; pi < 4; pi++) {
            uint32_t r0, r1, r2, r3;
            ldsm_x4(r0, r1, r2, r3, smBL + b_off[pi] + kadd);
            bfr[pi * 2][0] = r0; bfr[pi * 2][1] = r1;
            bfr[pi * 2 + 1][0] = r2; bfr[pi * 2 + 1][1] = r3;
        }
        #pragma unroll
        for (int ni = 0; ni < 8; ni++) {
            mma16816(acc[0][ni], afr[0], bfr[ni]);
            mma16816(acc[1][ni], afr[1], bfr[ni]);
        }
    }

    // ---- reload A tile with A_lo ----
    __syncthreads();
    #pragma unroll
    for (int i = tid; i < 128 * CR; i += 256) {
        int r = i / CR, c16 = i % CR;
        int doff = r * PITCH + c16 * 16;
        uint4 vl = make_uint4(0, 0, 0, 0);
        if (row0 + r < M) {
            if (NORM) {
                float h[8];
                z_to_h8(g_zh + (size_t)(row0 + r) * HID + c16 * 8, s_sc, s_sh, c16 * 8, h);
                __nv_bfloat162* o = (__nv_bfloat162*)&vl;
                #pragma unroll
                for (int j = 0; j < 4; j++) {
                    float h0 = h[2 * j], h1 = h[2 * j + 1];
                    __nv_bfloat16 hi0 = __float2bfloat16(h0);
                    __nv_bfloat16 hi1 = __float2bfloat16(h1);
                    o[j] = __nv_bfloat162(__float2bfloat16(h0 - __bfloat162float(hi0)),
                                          __float2bfloat16(h1 - __bfloat162float(hi1)));
                }
            } else {
                vl = a_lo[(size_t)(row0 + r) * 16 + c16];
            }
        }
        *(uint4*)(smem + SM_A + doff) = vl;
    }
    __syncthreads();

    // ---- phase 2: A_lo x B_hi ----
    #pragma unroll
    for (int k16 = 0; k16 < KSTEPS; k16++) {
        uint32_t kadd = k16 * 32;
        uint32_t afr[2][4];
        #pragma unroll
        for (int mi = 0; mi < 2; mi++)
            ldsm_x4(afr[mi][0], afr[mi][1], afr[mi][2], afr[mi][3],
                    smA + a_off[mi] + kadd);
        uint32_t bfr[8][2];
        #pragma unroll
        for (int pi = 0; pi < 4; pi++) {
            uint32_t r0, r1, r2, r3;
            ldsm_x4(r0, r1, r2, r3, smBH + b_off[pi] + kadd);
            bfr[pi * 2][0] = r0; bfr[pi * 2][1] = r1;
            bfr[pi * 2 + 1][0] = r2; bfr[pi * 2 + 1][1] = r3;
        }
        #pragma unroll
        for (int ni = 0; ni < 8; ni++) {
            mma16816(acc[0][ni], afr[0], bfr[ni]);
            mma16816(acc[1][ni], afr[1], bfr[ni]);
        }
    }

    // ---- epilogue: half 0 -> g_yh (fp16), half 1 -> g_zh (fp16 + bias) ----
    __half* O = half ? g_zh : g_yh;
    #pragma unroll
    for (int mi = 0; mi < 2; mi++) {
        int r0 = row0 + wm * 32 + mi * 16 + (lane >> 2);
        #pragma unroll
        for (int ni = 0; ni < 8; ni++) {
            int c = wn * 64 + ni * 8 + (lane & 3) * 2;
            float bx = 0.f, by = 0.f;
            if (half) { bx = bias[c]; by = bias[c + 1]; }
            if (r0 < M) {
                __half2 v = __floats2half2_rn(acc[mi][ni][0] + bx, acc[mi][ni][1] + by);
                *(__half2*)&O[(size_t)r0 * HID + c] = v;
            }
            if (r0 + 8 < M) {
                __half2 v = __floats2half2_rn(acc[mi][ni][2] + bx, acc[mi][ni][3] + by);
                *(__half2*)&O[(size_t)(r0 + 8) * HID + c] = v;
            }
        }
    }
}

// ---------------- gather-mean + fused BN stats ------------------------------
__global__ void aggregate_kernel(int N, int layer) {
    __shared__ float sh_s[8][132];
    __shared__ float sh_q[8][132];
    int wid = threadIdx.x >> 5;
    int lane = threadIdx.x & 31;
    int d = blockIdx.x * 8 + wid;

    float4 z = make_float4(0.f, 0.f, 0.f, 0.f);
    if (d < N) {
        int s0 = g_row_start[d];
        int s1 = g_row_start[d + 1];
        int deg = s1 - s0;
        float inv = 1.0f / (float)(deg > 1 ? deg : 1);
        const uint2* Y = (const uint2*)g_yh;

        float4 acc = make_float4(0.f, 0.f, 0.f, 0.f);
        int j = s0;
        for (; j + 3 < s1; j += 4) {
            uint2 ua = Y[(size_t)g_esrc[j] * 32 + lane];
            uint2 ub = Y[(size_t)g_esrc[j + 1] * 32 + lane];
            uint2 uc = Y[(size_t)g_esrc[j + 2] * 32 + lane];
            uint2 ud = Y[(size_t)g_esrc[j + 3] * 32 + lane];
            float2 a0 = __half22float2(*(__half2*)&ua.x), a1 = __half22float2(*(__half2*)&ua.y);
            float2 b0 = __half22float2(*(__half2*)&ub.x), b1 = __half22float2(*(__half2*)&ub.y);
            float2 c0 = __half22float2(*(__half2*)&uc.x), c1 = __half22float2(*(__half2*)&uc.y);
            float2 d0 = __half22float2(*(__half2*)&ud.x), d1 = __half22float2(*(__half2*)&ud.y);
            acc.x += (a0.x + b0.x) + (c0.x + d0.x);
            acc.y += (a0.y + b0.y) + (c0.y + d0.y);
            acc.z += (a1.x + b1.x) + (c1.x + d1.x);
            acc.w += (a1.y + b1.y) + (c1.y + d1.y);
        }
        for (; j < s1; j++) {
            uint2 ua = Y[(size_t)g_esrc[j] * 32 + lane];
            float2 a0 = __half22float2(*(__half2*)&ua.x), a1 = __half22float2(*(__half2*)&ua.y);
            acc.x += a0.x; acc.y += a0.y; acc.z += a1.x; acc.w += a1.y;
        }

        uint2 uz = ((const uint2*)g_zh)[(size_t)d * 32 + lane];
        float2 z01 = __half22float2(*(__half2*)&uz.x);
        float2 z23 = __half22float2(*(__half2*)&uz.y);
        z.x = fmaf(acc.x, inv, z01.x);
        z.y = fmaf(acc.y, inv, z01.y);
        z.z = fmaf(acc.z, inv, z23.x);
        z.w = fmaf(acc.w, inv, z23.y);
        uint2 uo;
        *(__half2*)&uo.x = __floats2half2_rn(z.x, z.y);
        *(__half2*)&uo.y = __floats2half2_rn(z.z, z.w);
        ((uint2*)g_zh)[(size_t)d * 32 + lane] = uo;
    }

    // fused BN stats
    float4 q = make_float4(z.x * z.x, z.y * z.y, z.z * z.z, z.w * z.w);
    *(float4*)&sh_s[wid][4 * lane] = z;
    *(float4*)&sh_q[wid][4 * lane] = q;
    __syncthreads();
    int t = threadIdx.x;
    if (t < HID) {
        float s = 0.f;
        #pragma unroll
        for (int w = 0; w < 8; w++) s += sh_s[w][t];
        atomicAdd(&g_statp[layer][t][0], s);
    } else {
        int c = t - HID;
        float s = 0.f;
        #pragma unroll
        for (int w = 0; w < 8; w++) s += sh_q[w][c];
        atomicAdd(&g_statp[layer][HID + c][0], s);
    }
}

// ---------------- fused norm + global mean pool + MLP head ------------------
__global__ void pool_head_kernel(const float* __restrict__ gamma,
                                 const float* __restrict__ beta,
                                 const float* __restrict__ Wh1,
                                 const float* __restrict__ bh1,
                                 const float* __restrict__ Wh2,
                                 const float* __restrict__ bh2,
                                 float* __restrict__ out, int G, int N)
{
    __shared__ float s_sc[HID];
    __shared__ float s_sh[HID];
    __shared__ float pooled[HID];
    __shared__ float sred[2];
    int g = blockIdx.x;
    int t = threadIdx.x;   // 0..127
    if (g >= G) return;

    if (t < HID) {
        float inv_m = 1.0f / (float)N;
        float mu = g_statp[2][t][0] * inv_m;
        float var = fmaxf(g_statp[2][HID + t][0] * inv_m - mu * mu, 0.f);
        float sc = gamma[t] * rsqrtf(var + EPS);
        s_sc[t] = sc;
        s_sh[t] = beta[t] - mu * sc;
    }
    __syncthreads();

    int r0 = g_gstart[g];
    int r1 = g_gstart[g + 1];
    float sc = s_sc[t], sh = s_sh[t];
    float s = 0.f;
    for (int r = r0; r < r1; r++) {
        float z = __half2float(g_zh[(size_t)r * HID + t]);
        s += fmaxf(fmaf(z, sc, sh), 0.f);
    }
    int cnt = r1 - r0;
    pooled[t] = s / (float)(cnt > 1 ? cnt : 1);
    __syncthreads();

    if (t < HIDH) {
        float acc = bh1[t];
        #pragma unroll 8
        for (int k = 0; k < HID; k++)
            acc = fmaf(pooled[k], Wh1[k * HIDH + t], acc);
        float v = fmaxf(acc, 0.f) * Wh2[t];
        #pragma unroll
        for (int off = 16; off; off >>= 1)
            v += __shfl_down_sync(0xffffffff, v, off);
        if ((t & 31) == 0) sred[t >> 5] = v;
    }
    __syncthreads();
    if (t == 0) out[g] = sred[0] + sred[1] + bh2[0];
}

// ---------------- launch ----------------
extern "C" void kernel_launch(void* const* d_in, const int* in_sizes, int n_in,
                              void* d_out, int out_size) {
    const float* x     = (const float*)d_in[0];
    const void*  ei    = d_in[1];
    const void*  batch = d_in[2];

    const float* W_n0 = (const float*)d_in[3];
    const float* b0   = (const float*)d_in[4];
    const float* W_r0 = (const float*)d_in[5];
    const float* g0   = (const float*)d_in[6];
    const float* be0  = (const float*)d_in[7];

    const float* W_n1 = (const float*)d_in[8];
    const float* b1   = (const float*)d_in[9];
    const float* W_r1 = (const float*)d_in[10];
    const float* g1   = (const float*)d_in[11];
    const float* be1  = (const float*)d_in[12];

    const float* W_n2 = (const float*)d_in[13];
    const float* b2   = (const float*)d_in[14];
    const float* W_r2 = (const float*)d_in[15];
    const float* g2   = (const float*)d_in[16];
    const float* be2  = (const float*)d_in[17];

    const float* Wh1 = (const float*)d_in[18];
    const float* bh1 = (const float*)d_in[19];
    const float* Wh2 = (const float*)d_in[20];
    const float* bh2 = (const float*)d_in[21];

    float* out = (float*)d_out;

    const int N = in_sizes[2];
    const int E = in_sizes[1] / 2;
    const int G = out_size;
    const int IN_CH = in_sizes[0] / N;

    cudaFuncSetAttribute((const void*)gemm_mma_kernel<5, false>,
                         cudaFuncAttributeMaxDynamicSharedMemorySize, SM_TOTAL);
    cudaFuncSetAttribute((const void*)gemm_mma_kernel<8, false>,
                         cudaFuncAttributeMaxDynamicSharedMemorySize, SM_TOTAL);
    cudaFuncSetAttribute((const void*)gemm_mma_kernel<8, true>,
                         cudaFuncAttributeMaxDynamicSharedMemorySize, SM_TOTAL);

    // ---- prep: flag/zero, detect dtype, CSR, segments ----
    prep0_kernel<<<(N + 255) / 256, 256>>>(N);
    detect_kernel<<<8, 256>>>(ei, in_sizes[1]);
    int nscan = (N + SCAN_B - 1) / SCAN_B;
    count_edges_kernel<<<(E + 255) / 256, 256>>>(ei, E);
    scan1_kernel<<<nscan, SCAN_B>>>(N);
    scan2_kernel<<<1, 32>>>(nscan);
    scan3_kernel<<<(N + 255) / 256, 256>>>(N, E);
    fill_edges_kernel<<<(E + 255) / 256, 256>>>(ei, E);
    gstart_kernel<<<(N + 256) / 256, 256>>>(batch, N, G);

    // ---- bf16 split preprocessing ----
    convert_x_kernel<<<(N * KPAD + 255) / 256, 256>>>(x, N, IN_CH);
    {
        dim3 wgrid((256 * KPAD + 255) / 256, 3);
        prep_weights_kernel<<<wgrid, 256>>>(W_n0, W_r0, W_n1, W_r1, W_n2, W_r2, IN_CH);
    }

    dim3 gemm_grid((N + 127) / 128, 2);
    int agg_blocks = (N + 7) / 8;
    int ksteps0 = (IN_CH + 15) / 16;   // 5 for IN_CH=78

    const float* bb[3] = {b0, b1, b2};
    const float* gg[3] = {g0, g1, g2};
    const float* be[3] = {be0, be1, be2};

    for (int l = 0; l < 3; l++) {
        const uint4* ahi = nullptr;
        const uint4* alo = nullptr;
        const uint4* bhi;
        const uint4* blo;
        void* p;
        if (l == 0) {
            cudaGetSymbolAddress(&p, g_ax_hi); ahi = (const uint4*)p;
            cudaGetSymbolAddress(&p, g_ax_lo); alo = (const uint4*)p;
        }
        cudaGetSymbolAddress(&p, g_bw_hi); bhi = (const uint4*)p + (size_t)l * (256 * KPAD / 8);
        cudaGetSymbolAddress(&p, g_bw_lo); blo = (const uint4*)p + (size_t)l * (256 * KPAD / 8);

        if (l == 0) {
            if (ksteps0 <= 5)
                gemm_mma_kernel<5, false><<<gemm_grid, 256, SM_TOTAL>>>(
                    ahi, alo, bhi, blo, bb[l], nullptr, nullptr, 0, N);
            else
                gemm_mma_kernel<8, false><<<gemm_grid, 256, SM_TOTAL>>>(
                    ahi, alo, bhi, blo, bb[l], nullptr, nullptr, 0, N);
        } else {
            gemm_mma_kernel<8, true><<<gemm_grid, 256, SM_TOTAL>>>(
                nullptr, nullptr, bhi, blo, bb[l], gg[l - 1], be[l - 1], l - 1, N);
        }
        aggregate_kernel<<<agg_blocks, 256>>>(N, l);
    }

    pool_head_kernel<<<G, HID>>>(gg[2], be[2], Wh1, bh1, Wh2, bh2, out, G, N);
}